// round 12
// baseline (speedup 1.0000x reference)
#include <cuda_runtime.h>
#include <cuda_bf16.h>
#include <math.h>
#include <stdint.h>

#define NROWS 65536
#define D 256
#define K 1024
#define QSIZE (NROWS*D)
#define CAND_M 1e-3f
#define NCAND 24

// ---------------- scratch ----------------
__device__ __align__(128) float g_eT[K*D];
__device__ __align__(128) float g_en2[K];
__device__ __align__(128) float g_zn2[NROWS];
__device__ int   g_idx[NROWS];
__device__ float g_part[8192];
__device__ int   g_hist[K];
__device__ __align__(128) __nv_bfloat16 g_ebh[K*D];
__device__ __align__(128) __nv_bfloat16 g_ebl[K*D];
__device__ int   g_flag[NROWS];
__device__ int   g_nflag;
__device__ int   g_bad;
__device__ short g_cand[(size_t)NROWS*NCAND];
__device__ int   g_cnt[NROWS];

// ---------------- asm helpers ----------------
__device__ __forceinline__ uint32_t smem_u32(const void* p) {
    uint32_t a;
    asm("{ .reg .u64 t; cvta.to.shared.u64 t, %1; cvt.u32.u64 %0, t; }" : "=r"(a) : "l"(p));
    return a;
}
__device__ __forceinline__ void ldsm4(uint32_t* r, uint32_t addr) {
    asm volatile("ldmatrix.sync.aligned.m8n8.x4.shared.b16 {%0,%1,%2,%3}, [%4];"
        : "=r"(r[0]), "=r"(r[1]), "=r"(r[2]), "=r"(r[3]) : "r"(addr));
}
__device__ __forceinline__ void mma16816(float* c, const uint32_t* a, uint32_t b0, uint32_t b1) {
    asm volatile("mma.sync.aligned.m16n8k16.row.col.f32.bf16.bf16.f32 "
        "{%0,%1,%2,%3}, {%4,%5,%6,%7}, {%8,%9}, {%0,%1,%2,%3};"
        : "+f"(c[0]), "+f"(c[1]), "+f"(c[2]), "+f"(c[3])
        : "r"(a[0]), "r"(a[1]), "r"(a[2]), "r"(a[3]), "r"(b0), "r"(b1));
}
__device__ __forceinline__ void cp16(uint32_t dst, const void* src) {
    asm volatile("cp.async.cg.shared.global [%0], [%1], 16;" :: "r"(dst), "l"(src) : "memory");
}
#define CP_COMMIT() asm volatile("cp.async.commit_group;" ::: "memory")
#define CP_WAIT1()  asm volatile("cp.async.wait_group 1;" ::: "memory")
#define CP_WAIT0()  asm volatile("cp.async.wait_group 0;" ::: "memory")

__device__ __forceinline__ void fma2(unsigned long long& acc,
                                     unsigned long long a, unsigned long long b) {
    asm("fma.rn.f32x2 %0, %1, %2, %0;" : "+l"(acc) : "l"(a), "l"(b));
}
__device__ __forceinline__ unsigned long long pack2(float x) {
    unsigned long long r;
    asm("mov.b64 %0, {%1, %2};" : "=l"(r) : "f"(x), "f"(x));
    return r;
}
__device__ __forceinline__ void unpack2(float& lo, float& hi, unsigned long long v) {
    asm("mov.b64 {%0, %1}, %2;" : "=f"(lo), "=f"(hi) : "l"(v));
}

// ---------------- init + en2 ----------------
__global__ void k_init_en2(const float* __restrict__ e) {
    int t = blockIdx.x * blockDim.x + threadIdx.x;
    if (t == 0) { g_nflag = 0; g_bad = 0; }
    if (t >= K) return;
    g_hist[t] = 0;
    float s = 0.f;
    for (int d = 0; d < D; ++d) {
        float v = e[d * K + t];
        s = __fadd_rn(s, __fmul_rn(v, v));
    }
    g_en2[t] = s;
}

__global__ void k_prep(const float* __restrict__ e) {
    __shared__ float t[32][33];
    int kb = blockIdx.x * 32, db = blockIdx.y * 32;
    int tx = threadIdx.x, ty = threadIdx.y;
    #pragma unroll
    for (int i = 0; i < 32; i += 8)
        t[ty + i][tx] = e[(db + ty + i) * K + kb + tx];
    __syncthreads();
    #pragma unroll
    for (int i = 0; i < 32; i += 8) {
        float v = t[tx][ty + i];
        int off = (kb + ty + i) * D + db + tx;
        g_eT[off] = v;
        __nv_bfloat16 hb = __float2bfloat16_rn(v);
        g_ebh[off] = hb;
        g_ebl[off] = __float2bfloat16_rn(v - __bfloat162float(hb));
    }
}

__global__ void k_zn2(const float* __restrict__ z) {
    __shared__ float sz[32][257];
    int row0 = blockIdx.x * 32;
    int tid = threadIdx.x;
    #pragma unroll
    for (int i = 0; i < 32; i++) {
        int l = i * 256 + tid;
        int r = l >> 8, d = l & 255;
        sz[r][d] = z[(size_t)(row0 + r) * D + d];
    }
    __syncthreads();
    if (tid < 32) {
        float s = 0.f;
        for (int d = 0; d < D; ++d) {
            float v = sz[tid][d];
            s = __fadd_rn(s, __fmul_rn(v, v));
        }
        g_zn2[row0 + tid] = s;
    }
}

// ---------------- phaseA: bf16x3 HMMA + candidate generation (chunk-skip) ----------------
#define PITCH 528
#define SA_LO 67584
#define SB_OFF 135168
#define SB_BUF 33792
#define SB_HL  16896
#define SEN2   202752                    // 2 x 32 floats
#define SDIST  203008                    // 128 x 34 floats = 17408
#define SCAND  220416                    // 128 x 24 shorts = 6144
#define SMEM_TOT 226560

__device__ __forceinline__ void stageB(char* smem, uint32_t sb, int chunk, int buf, int tid) {
    #pragma unroll
    for (int i = 0; i < 8; i++) {
        int lin = i * 256 + tid;
        int hl = lin >> 10, rem = lin & 1023, r = rem >> 5, s = rem & 31;
        const __nv_bfloat16* src = (hl ? g_ebl : g_ebh)
            + ((size_t)(chunk * 32 + r) << 8) + (s << 3);
        uint32_t dst = sb + SB_OFF + buf * SB_BUF + hl * SB_HL + r * PITCH + (s << 4);
        cp16(dst, src);
    }
    if (tid < 32)
        *(float*)(smem + SEN2 + buf * 128 + tid * 4) = g_en2[chunk * 32 + tid];
}

__global__ __launch_bounds__(256, 1)
void k_phaseA(const float* __restrict__ z) {
    extern __shared__ char smem[];
    uint32_t sb = smem_u32(smem);
    int tid = threadIdx.x, lane = tid & 31, wid = tid >> 5;
    int warp_m = wid >> 1, warp_n = wid & 1;
    int row0 = blockIdx.x * 128;

    #pragma unroll 4
    for (int i = 0; i < 32; i++) {
        int gi = i * 256 + tid;
        int r = gi >> 6, c4 = (gi & 63) << 2;
        const float4 v = *(const float4*)(z + ((size_t)(row0 + r) << 8) + c4);
        __nv_bfloat16 h0 = __float2bfloat16_rn(v.x), h1 = __float2bfloat16_rn(v.y);
        __nv_bfloat16 h2 = __float2bfloat16_rn(v.z), h3 = __float2bfloat16_rn(v.w);
        __nv_bfloat16 l0 = __float2bfloat16_rn(v.x - __bfloat162float(h0));
        __nv_bfloat16 l1 = __float2bfloat16_rn(v.y - __bfloat162float(h1));
        __nv_bfloat16 l2 = __float2bfloat16_rn(v.z - __bfloat162float(h2));
        __nv_bfloat16 l3 = __float2bfloat16_rn(v.w - __bfloat162float(h3));
        uint2 hw, lw;
        hw.x = (uint32_t)__bfloat16_as_ushort(h0) | ((uint32_t)__bfloat16_as_ushort(h1) << 16);
        hw.y = (uint32_t)__bfloat16_as_ushort(h2) | ((uint32_t)__bfloat16_as_ushort(h3) << 16);
        lw.x = (uint32_t)__bfloat16_as_ushort(l0) | ((uint32_t)__bfloat16_as_ushort(l1) << 16);
        lw.y = (uint32_t)__bfloat16_as_ushort(l2) | ((uint32_t)__bfloat16_as_ushort(l3) << 16);
        int off = r * PITCH + (c4 << 1);
        *(uint2*)(smem + off) = hw;
        *(uint2*)(smem + SA_LO + off) = lw;
    }
    stageB(smem, sb, 0, 0, tid);
    CP_COMMIT();

    uint32_t a_off = sb + (uint32_t)(warp_m * 32 + (lane & 15)) * PITCH + ((lane >> 4) << 4);
    uint32_t b_off = sb + SB_OFF
        + (uint32_t)(warp_n * 16 + (lane & 7) + ((lane >> 4) << 3)) * PITCH
        + (((lane >> 3) & 1) << 4);

    float* sd = (float*)(smem + SDIST);
    short* scand = (short*)(smem + SCAND);
    float rmin = INFINITY;
    int nc = 0, ovf = 0;

    for (int ch = 0; ch < 32; ch++) {
        int buf = ch & 1;
        if (ch + 1 < 32) { stageB(smem, sb, ch + 1, buf ^ 1, tid); CP_COMMIT(); CP_WAIT1(); }
        else CP_WAIT0();
        __syncthreads();

        float acc[2][2][4];
        #pragma unroll
        for (int mt = 0; mt < 2; mt++)
            #pragma unroll
            for (int nt = 0; nt < 2; nt++)
                #pragma unroll
                for (int q = 0; q < 4; q++) acc[mt][nt][q] = 0.f;

        #pragma unroll
        for (int seg = 0; seg < 3; seg++) {
            uint32_t ab = a_off + (seg == 2 ? SA_LO : 0);
            uint32_t bb = b_off + buf * SB_BUF + (seg == 1 ? SB_HL : 0);
            #pragma unroll
            for (int kk = 0; kk < 16; kk++) {
                uint32_t A0[4], A1[4], B[4];
                ldsm4(A0, ab + kk * 32);
                ldsm4(A1, ab + kk * 32 + 16 * PITCH);
                ldsm4(B, bb + kk * 32);
                mma16816(acc[0][0], A0, B[0], B[1]);
                mma16816(acc[0][1], A0, B[2], B[3]);
                mma16816(acc[1][0], A1, B[0], B[1]);
                mma16816(acc[1][1], A1, B[2], B[3]);
            }
        }

        const float* en2s = (const float*)(smem + SEN2 + buf * 128);
        #pragma unroll
        for (int mt = 0; mt < 2; mt++) {
            #pragma unroll
            for (int nt = 0; nt < 2; nt++) {
                int cb = warp_n * 16 + nt * 8 + (lane & 3) * 2;
                float e0 = en2s[cb], e1 = en2s[cb + 1];
                #pragma unroll
                for (int half = 0; half < 2; half++) {
                    int r = warp_m * 32 + mt * 16 + half * 8 + (lane >> 2);
                    float2 dp;
                    dp.x = __fsub_rn(e0, 2.0f * acc[mt][nt][half * 2]);
                    dp.y = __fsub_rn(e1, 2.0f * acc[mt][nt][half * 2 + 1]);
                    *(float2*)&sd[r * 34 + cb] = dp;
                }
            }
        }
        __syncthreads();
        // per-row: branch-free chunk-min first; only scan-append when chunk can contribute
        if (tid < 128) {
            const float* rowd = &sd[tid * 34];
            float cmin = rowd[0];
            #pragma unroll
            for (int c = 1; c < 32; c++) cmin = fminf(cmin, rowd[c]);
            if (cmin < rmin + CAND_M) {
                #pragma unroll
                for (int c = 0; c < 32; c++) {
                    float a = rowd[c];
                    if (a < rmin + CAND_M) {
                        if (nc < NCAND) scand[tid * NCAND + nc] = (short)(ch * 32 + c);
                        else ovf = 1;
                        nc++;
                        if (a < rmin) rmin = a;
                    }
                }
            }
        }
        __syncthreads();
    }

    if (tid < 128) {
        int row = row0 + tid;
        if (ovf) {
            g_cnt[row] = -1;
            int p = atomicAdd(&g_nflag, 1);
            g_flag[p] = row;
        } else {
            g_cnt[row] = nc;
            for (int c = 0; c < nc; c++)
                g_cand[(size_t)row * NCAND + c] = scand[tid * NCAND + c];
        }
    }
}

// ---------------- k_cand: exact re-rank via eT (coalesced per-lane streams) ----------------
__global__ void k_cand(const float* __restrict__ z) {
    int warp = threadIdx.x >> 5, lane = threadIdx.x & 31;
    int row = blockIdx.x * 8 + warp;
    int cnt = g_cnt[row];
    if (cnt < 0) return;                       // overflow -> rescued
    int code = (lane < cnt) ? (int)g_cand[(size_t)row * NCAND + lane] : -1;
    float dist = INFINITY;
    if (lane < cnt) {
        const float* zr = z + ((size_t)row << 8);
        const float* er = &g_eT[(size_t)code << 8];   // same values as e[:,code], same order
        float t = 0.f;
        #pragma unroll 8
        for (int d = 0; d < 256; d++)
            t = fmaf(zr[d], er[d], t);
        dist = __fsub_rn(__fadd_rn(g_zn2[row], g_en2[code]), 2.0f * t);
    }
    int ord = lane, bc = code;
    float bv = dist;
    #pragma unroll
    for (int off = 16; off; off >>= 1) {
        float ov = __shfl_xor_sync(0xffffffffu, bv, off);
        int oo = __shfl_xor_sync(0xffffffffu, ord, off);
        int oc = __shfl_xor_sync(0xffffffffu, bc, off);
        if (ov < bv || (ov == bv && oo < ord)) { bv = ov; ord = oo; bc = oc; }
    }
    if (lane == 0) g_idx[row] = bc;
}

// ---------------- block-batched exact rescue (overflow rows) ----------------
#define RSP 260
#define RS_SMEM ((32*RSP + 64*RSP + 256 + 256) * 4)

__global__ __launch_bounds__(256, 1)
void k_rescue(const float* __restrict__ z) {
    extern __shared__ float rs[];
    float* sz = rs;
    float* se = rs + 32 * RSP;
    float* mbv = se + 64 * RSP;
    int*   mbi = (int*)(mbv + 256);
    int tid = threadIdx.x;
    int r = tid >> 3, cs = tid & 7;
    int n = g_nflag;

    for (int base = blockIdx.x * 32; base < n; base += gridDim.x * 32) {
        int cnt = min(32, n - base);
        for (int i = tid; i < cnt * 64; i += 256) {
            int rr = i >> 6, q = (i & 63) << 2;
            int row = g_flag[base + rr];
            float4 vv = *(const float4*)&z[((size_t)row << 8) + q];
            sz[rr * RSP + q] = vv.x; sz[rr * RSP + q + 1] = vv.y;
            sz[rr * RSP + q + 2] = vv.z; sz[rr * RSP + q + 3] = vv.w;
        }
        float myzn2 = (r < cnt) ? g_zn2[g_flag[base + r]] : 0.f;
        float bv = INFINITY; int bi = 0;
        for (int cc = 0; cc < 16; cc++) {
            __syncthreads();
            for (int i = tid; i < 64 * 64; i += 256) {
                int c = i >> 6, q = (i & 63) << 2;
                float4 vv = *(const float4*)&g_eT[((size_t)(cc * 64 + c) << 8) + q];
                se[c * RSP + q] = vv.x; se[c * RSP + q + 1] = vv.y;
                se[c * RSP + q + 2] = vv.z; se[c * RSP + q + 3] = vv.w;
            }
            __syncthreads();
            if (r < cnt) {
                #pragma unroll
                for (int m = 0; m < 8; m++) {
                    int c = cs + 8 * m;
                    float t = 0.f;
                    #pragma unroll 8
                    for (int d = 0; d < 256; d++)
                        t = fmaf(sz[r * RSP + d], se[c * RSP + d], t);
                    int cde = cc * 64 + c;
                    float dist = __fsub_rn(__fadd_rn(myzn2, g_en2[cde]), 2.0f * t);
                    if (dist < bv) { bv = dist; bi = cde; }
                }
            }
        }
        mbv[tid] = bv; mbi[tid] = bi;
        __syncthreads();
        if (tid < cnt) {
            float fb = mbv[tid * 8]; int fi = mbi[tid * 8];
            #pragma unroll
            for (int s2 = 1; s2 < 8; s2++) {
                float vv = mbv[tid * 8 + s2]; int ii = mbi[tid * 8 + s2];
                if (vv < fb || (vv == fb && ii < fi)) { fb = vv; fi = ii; }
            }
            g_idx[g_flag[base + tid]] = fi;
        }
        __syncthreads();
    }
}

// ---------------- sampled exact index checker (256 rows) ----------------
__global__ void k_check(const float* __restrict__ z, const float* __restrict__ e) {
    __shared__ float srow[8][256];
    int warp = threadIdx.x >> 5, lane = threadIdx.x & 31;
    int row = (blockIdx.x * 8 + warp) * 256 + 128;
    for (int d = lane; d < 256; d += 32) srow[warp][d] = z[((size_t)row << 8) + d];
    __syncwarp();
    float zn2 = g_zn2[row];
    float bv = INFINITY; int bi = 0;
    for (int c = 0; c < 32; c++) {
        int code = c * 32 + lane;
        float t = 0.f;
        #pragma unroll 8
        for (int d = 0; d < 256; d++)
            t = fmaf(srow[warp][d], e[d * K + code], t);
        float dist = __fsub_rn(__fadd_rn(zn2, g_en2[code]), 2.0f * t);
        if (dist < bv) { bv = dist; bi = code; }
    }
    #pragma unroll
    for (int off = 16; off; off >>= 1) {
        float ov = __shfl_xor_sync(0xffffffffu, bv, off);
        int oi = __shfl_xor_sync(0xffffffffu, bi, off);
        if (ov < bv || (ov == bv && oi < bi)) { bv = ov; bi = oi; }
    }
    if (lane == 0 && g_idx[row] != bi) atomicAdd(&g_bad, 1);
}

// ---------------- conditional FFMA2 fp32 fallback (R6, bit-exact) ----------------
#define BM 128
#define BN 128
#define BK 16
#define TM 8
#define TN 8
#define BMP 132

__global__ __launch_bounds__(256, 2)
void k_fallback(const float* __restrict__ z, const float* __restrict__ e) {
    if (g_bad == 0) return;
    __shared__ float s_zT[BK][BMP];
    __shared__ float s_e[BK][BN];
    __shared__ float s_en2[BN];
    __shared__ float m_v[BM][16];
    __shared__ int   m_i[BM][16];

    int tid = threadIdx.x;
    int tx = tid & 15, ty = tid >> 4;
    int row0 = blockIdx.x * BM;

    float bestv[TM]; int besti[TM]; float my_zn2[TM];
    #pragma unroll
    for (int i = 0; i < TM; i++) {
        bestv[i] = INFINITY; besti[i] = 0;
        my_zn2[i] = g_zn2[row0 + ty * TM + i];
    }

    for (int kc = 0; kc < K; kc += BN) {
        __syncthreads();
        if (tid < BN) s_en2[tid] = g_en2[kc + tid];
        unsigned long long acc2[TM][TN / 2];
        #pragma unroll
        for (int i = 0; i < TM; i++)
            #pragma unroll
            for (int j = 0; j < TN / 2; j++) acc2[i][j] = 0ULL;
        for (int dk = 0; dk < D; dk += BK) {
            #pragma unroll
            for (int i = 0; i < 8; i++) {
                int l = i * 256 + tid;
                int r = l >> 4, d = l & 15;
                s_zT[d][r] = z[(size_t)(row0 + r) * D + dk + d];
                int d2 = l >> 7, k2 = l & 127;
                s_e[d2][k2] = e[(dk + d2) * K + kc + k2];
            }
            __syncthreads();
            #pragma unroll
            for (int d = 0; d < BK; d++) {
                float a[TM];
                float4 a0 = *(const float4*)&s_zT[d][ty * TM];
                float4 a1 = *(const float4*)&s_zT[d][ty * TM + 4];
                a[0]=a0.x; a[1]=a0.y; a[2]=a0.z; a[3]=a0.w;
                a[4]=a1.x; a[5]=a1.y; a[6]=a1.z; a[7]=a1.w;
                union { float4 v; unsigned long long u[2]; } bu0, bu1;
                bu0.v = *(const float4*)&s_e[d][tx * TN];
                bu1.v = *(const float4*)&s_e[d][tx * TN + 4];
                unsigned long long b2v[4] = { bu0.u[0], bu0.u[1], bu1.u[0], bu1.u[1] };
                #pragma unroll
                for (int i = 0; i < TM; i++) {
                    unsigned long long a2 = pack2(a[i]);
                    fma2(acc2[i][0], a2, b2v[0]);
                    fma2(acc2[i][1], a2, b2v[1]);
                    fma2(acc2[i][2], a2, b2v[2]);
                    fma2(acc2[i][3], a2, b2v[3]);
                }
            }
            __syncthreads();
        }
        #pragma unroll
        for (int i = 0; i < TM; i++) {
            #pragma unroll
            for (int j2 = 0; j2 < TN / 2; j2++) {
                float t0, t1;
                unpack2(t0, t1, acc2[i][j2]);
                int j = 2 * j2;
                float dist0 = __fsub_rn(__fadd_rn(my_zn2[i], s_en2[tx * TN + j]), 2.0f * t0);
                float dist1 = __fsub_rn(__fadd_rn(my_zn2[i], s_en2[tx * TN + j + 1]), 2.0f * t1);
                int code = kc + tx * TN + j;
                if (dist0 < bestv[i]) { bestv[i] = dist0; besti[i] = code; }
                if (dist1 < bestv[i]) { bestv[i] = dist1; besti[i] = code + 1; }
            }
        }
    }
    __syncthreads();
    #pragma unroll
    for (int i = 0; i < TM; i++) {
        m_v[ty * TM + i][tx] = bestv[i];
        m_i[ty * TM + i][tx] = besti[i];
    }
    __syncthreads();
    if (tid < BM) {
        float bv = m_v[tid][0]; int bi = m_i[tid][0];
        #pragma unroll
        for (int t = 1; t < 16; t++) {
            float v = m_v[tid][t]; int ii = m_i[tid][t];
            if (v < bv || (v == bv && ii < bi)) { bv = v; bi = ii; }
        }
        g_idx[row0 + tid] = bi;
    }
}

// ---------------- gather + losses ----------------
__global__ void k_gather(const float* __restrict__ z, float* __restrict__ out) {
    int warp = threadIdx.x >> 5, lane = threadIdx.x & 31;
    int row = blockIdx.x * 8 + warp;
    int k = g_idx[row];
    if (lane == 0) {
        atomicAdd(&g_hist[k], 1);
        out[QSIZE + row] = (float)k;
    }
    const float* er = &g_eT[k * D];
    const float* zr = z + (size_t)row * D;
    float* qr = out + (size_t)row * D;
    float ss = 0.f;
    #pragma unroll
    for (int d = lane; d < D; d += 32) {
        float q = er[d];
        float zv = zr[d];
        float diff = q - zv;
        ss = fmaf(diff, diff, ss);
        qr[d] = __fadd_rn(zv, __fsub_rn(q, zv));
    }
    #pragma unroll
    for (int off = 16; off; off >>= 1)
        ss += __shfl_xor_sync(0xffffffffu, ss, off);
    __shared__ float wsum[8];
    if (lane == 0) wsum[warp] = ss;
    __syncthreads();
    if (threadIdx.x == 0) {
        float t = 0.f;
        for (int w = 0; w < 8; w++) t += wsum[w];
        g_part[blockIdx.x] = t;
    }
}

__global__ void k_final(float* __restrict__ out) {
    __shared__ double sd2[256];
    int t = threadIdx.x;
    double s = 0.0;
    for (int i = t; i < 8192; i += 256) s += (double)g_part[i];
    sd2[t] = s;
    __syncthreads();
    for (int off = 128; off; off >>= 1) {
        if (t < off) sd2[t] += sd2[t + off];
        __syncthreads();
    }
    if (t == 0) {
        float vq = (float)(sd2[0] / (double)QSIZE);
        out[QSIZE + NROWS + 0] = vq;
        out[QSIZE + NROWS + 1] = 0.25f * vq;
        float ent = 0.f;
        for (int i = 0; i < K; i++) {
            float p = __fmul_rn((float)g_hist[i], 1.0f / 65536.0f);
            ent = __fadd_rn(ent, __fmul_rn(p, logf(__fadd_rn(p, 1e-10f))));
        }
        out[QSIZE + NROWS + 2] = expf(-ent);
    }
}

extern "C" void kernel_launch(void* const* d_in, const int* in_sizes, int n_in,
                              void* d_out, int out_size) {
    const float* z = (const float*)d_in[0];
    const float* e = (const float*)d_in[1];
    float* out = (float*)d_out;

    cudaFuncSetAttribute(k_phaseA, cudaFuncAttributeMaxDynamicSharedMemorySize, SMEM_TOT);
    cudaFuncSetAttribute(k_rescue, cudaFuncAttributeMaxDynamicSharedMemorySize, RS_SMEM);

    k_init_en2<<<4, 256>>>(e);                             // idx 0
    k_zn2<<<NROWS / 32, 256>>>(z);                         // idx 1
    k_prep<<<dim3(K / 32, D / 32), dim3(32, 8)>>>(e);      // idx 2
    k_phaseA<<<NROWS / 128, 256, SMEM_TOT>>>(z);           // idx 3  <- PROFILED
    k_cand<<<NROWS / 8, 256>>>(z);                         // idx 4
    k_rescue<<<256, 256, RS_SMEM>>>(z);                    // idx 5
    k_check<<<32, 256>>>(z, e);                            // idx 6
    k_fallback<<<NROWS / BM, 256>>>(z, e);                 // idx 7
    k_gather<<<NROWS / 8, 256>>>(z, out);                  // idx 8
    k_final<<<1, 256>>>(out);                              // idx 9
}

// round 13
// speedup vs baseline: 1.0410x; 1.0410x over previous
#include <cuda_runtime.h>
#include <cuda_bf16.h>
#include <math.h>
#include <stdint.h>

#define NROWS 65536
#define D 256
#define K 1024
#define QSIZE (NROWS*D)
#define CAND_M 4e-4f
#define NCAND 24

// ---------------- scratch ----------------
__device__ __align__(128) float g_eT[K*D];
__device__ __align__(128) float g_en2[K];
__device__ __align__(128) float g_zn2[NROWS];
__device__ int   g_idx[NROWS];
__device__ float g_part[8192];
__device__ int   g_hist[K];
__device__ __align__(128) __nv_bfloat16 g_ebh[K*D];
__device__ __align__(128) __nv_bfloat16 g_ebl[K*D];
__device__ int   g_flag[NROWS];
__device__ int   g_nflag;
__device__ int   g_bad;
__device__ short g_cand[(size_t)NROWS*NCAND];
__device__ int   g_cnt[NROWS];

// ---------------- asm helpers ----------------
__device__ __forceinline__ uint32_t smem_u32(const void* p) {
    uint32_t a;
    asm("{ .reg .u64 t; cvta.to.shared.u64 t, %1; cvt.u32.u64 %0, t; }" : "=r"(a) : "l"(p));
    return a;
}
__device__ __forceinline__ void ldsm4(uint32_t* r, uint32_t addr) {
    asm volatile("ldmatrix.sync.aligned.m8n8.x4.shared.b16 {%0,%1,%2,%3}, [%4];"
        : "=r"(r[0]), "=r"(r[1]), "=r"(r[2]), "=r"(r[3]) : "r"(addr));
}
__device__ __forceinline__ void mma16816(float* c, const uint32_t* a, uint32_t b0, uint32_t b1) {
    asm volatile("mma.sync.aligned.m16n8k16.row.col.f32.bf16.bf16.f32 "
        "{%0,%1,%2,%3}, {%4,%5,%6,%7}, {%8,%9}, {%0,%1,%2,%3};"
        : "+f"(c[0]), "+f"(c[1]), "+f"(c[2]), "+f"(c[3])
        : "r"(a[0]), "r"(a[1]), "r"(a[2]), "r"(a[3]), "r"(b0), "r"(b1));
}
__device__ __forceinline__ void cp16(uint32_t dst, const void* src) {
    asm volatile("cp.async.cg.shared.global [%0], [%1], 16;" :: "r"(dst), "l"(src) : "memory");
}
#define CP_COMMIT() asm volatile("cp.async.commit_group;" ::: "memory")
#define CP_WAIT1()  asm volatile("cp.async.wait_group 1;" ::: "memory")
#define CP_WAIT0()  asm volatile("cp.async.wait_group 0;" ::: "memory")

__device__ __forceinline__ void fma2(unsigned long long& acc,
                                     unsigned long long a, unsigned long long b) {
    asm("fma.rn.f32x2 %0, %1, %2, %0;" : "+l"(acc) : "l"(a), "l"(b));
}
__device__ __forceinline__ unsigned long long pack2(float x) {
    unsigned long long r;
    asm("mov.b64 %0, {%1, %2};" : "=l"(r) : "f"(x), "f"(x));
    return r;
}
__device__ __forceinline__ void unpack2(float& lo, float& hi, unsigned long long v) {
    asm("mov.b64 {%0, %1}, %2;" : "=f"(lo), "=f"(hi) : "l"(v));
}

// ---------------- setup: hist/flags + en2 + zn2 in ONE kernel (launch-slot economy) ----------------
__global__ void k_setup(const float* __restrict__ z, const float* __restrict__ e) {
    if (blockIdx.x >= 2048) {
        int t = (blockIdx.x - 2048) * 256 + threadIdx.x;
        if (t == 0) { g_nflag = 0; g_bad = 0; }
        if (t < K) {
            g_hist[t] = 0;
            float s = 0.f;
            for (int d = 0; d < D; ++d) {
                float v = e[d * K + t];
                s = __fadd_rn(s, __fmul_rn(v, v));
            }
            g_en2[t] = s;
        }
        return;
    }
    __shared__ float sz[32][257];
    int row0 = blockIdx.x * 32;
    int tid = threadIdx.x;
    #pragma unroll
    for (int i = 0; i < 32; i++) {
        int l = i * 256 + tid;
        int r = l >> 8, d = l & 255;
        sz[r][d] = z[(size_t)(row0 + r) * D + d];
    }
    __syncthreads();
    if (tid < 32) {
        float s = 0.f;
        for (int d = 0; d < D; ++d) {
            float v = sz[tid][d];
            s = __fadd_rn(s, __fmul_rn(v, v));
        }
        g_zn2[row0 + tid] = s;
    }
}

__global__ void k_prep(const float* __restrict__ e) {
    __shared__ float t[32][33];
    int kb = blockIdx.x * 32, db = blockIdx.y * 32;
    int tx = threadIdx.x, ty = threadIdx.y;
    #pragma unroll
    for (int i = 0; i < 32; i += 8)
        t[ty + i][tx] = e[(db + ty + i) * K + kb + tx];
    __syncthreads();
    #pragma unroll
    for (int i = 0; i < 32; i += 8) {
        float v = t[tx][ty + i];
        int off = (kb + ty + i) * D + db + tx;
        g_eT[off] = v;
        __nv_bfloat16 hb = __float2bfloat16_rn(v);
        g_ebh[off] = hb;
        g_ebl[off] = __float2bfloat16_rn(v - __bfloat162float(hb));
    }
}

// ---------------- phaseA: bf16x3 HMMA + candidate generation (chunk-skip) ----------------
#define PITCH 528
#define SA_LO 67584
#define SB_OFF 135168
#define SB_BUF 33792
#define SB_HL  16896
#define SEN2   202752                    // 2 x 32 floats
#define SDIST  203008                    // 128 x 34 floats = 17408
#define SCAND  220416                    // 128 x 24 shorts = 6144
#define SMEM_TOT 226560

__device__ __forceinline__ void stageB(char* smem, uint32_t sb, int chunk, int buf, int tid) {
    #pragma unroll
    for (int i = 0; i < 8; i++) {
        int lin = i * 256 + tid;
        int hl = lin >> 10, rem = lin & 1023, r = rem >> 5, s = rem & 31;
        const __nv_bfloat16* src = (hl ? g_ebl : g_ebh)
            + ((size_t)(chunk * 32 + r) << 8) + (s << 3);
        uint32_t dst = sb + SB_OFF + buf * SB_BUF + hl * SB_HL + r * PITCH + (s << 4);
        cp16(dst, src);
    }
    if (tid < 32)
        *(float*)(smem + SEN2 + buf * 128 + tid * 4) = g_en2[chunk * 32 + tid];
}

__global__ __launch_bounds__(256, 1)
void k_phaseA(const float* __restrict__ z) {
    extern __shared__ char smem[];
    uint32_t sb = smem_u32(smem);
    int tid = threadIdx.x, lane = tid & 31, wid = tid >> 5;
    int warp_m = wid >> 1, warp_n = wid & 1;
    int row0 = blockIdx.x * 128;

    #pragma unroll 4
    for (int i = 0; i < 32; i++) {
        int gi = i * 256 + tid;
        int r = gi >> 6, c4 = (gi & 63) << 2;
        const float4 v = *(const float4*)(z + ((size_t)(row0 + r) << 8) + c4);
        __nv_bfloat16 h0 = __float2bfloat16_rn(v.x), h1 = __float2bfloat16_rn(v.y);
        __nv_bfloat16 h2 = __float2bfloat16_rn(v.z), h3 = __float2bfloat16_rn(v.w);
        __nv_bfloat16 l0 = __float2bfloat16_rn(v.x - __bfloat162float(h0));
        __nv_bfloat16 l1 = __float2bfloat16_rn(v.y - __bfloat162float(h1));
        __nv_bfloat16 l2 = __float2bfloat16_rn(v.z - __bfloat162float(h2));
        __nv_bfloat16 l3 = __float2bfloat16_rn(v.w - __bfloat162float(h3));
        uint2 hw, lw;
        hw.x = (uint32_t)__bfloat16_as_ushort(h0) | ((uint32_t)__bfloat16_as_ushort(h1) << 16);
        hw.y = (uint32_t)__bfloat16_as_ushort(h2) | ((uint32_t)__bfloat16_as_ushort(h3) << 16);
        lw.x = (uint32_t)__bfloat16_as_ushort(l0) | ((uint32_t)__bfloat16_as_ushort(l1) << 16);
        lw.y = (uint32_t)__bfloat16_as_ushort(l2) | ((uint32_t)__bfloat16_as_ushort(l3) << 16);
        int off = r * PITCH + (c4 << 1);
        *(uint2*)(smem + off) = hw;
        *(uint2*)(smem + SA_LO + off) = lw;
    }
    stageB(smem, sb, 0, 0, tid);
    CP_COMMIT();

    uint32_t a_off = sb + (uint32_t)(warp_m * 32 + (lane & 15)) * PITCH + ((lane >> 4) << 4);
    uint32_t b_off = sb + SB_OFF
        + (uint32_t)(warp_n * 16 + (lane & 7) + ((lane >> 4) << 3)) * PITCH
        + (((lane >> 3) & 1) << 4);

    float* sd = (float*)(smem + SDIST);
    short* scand = (short*)(smem + SCAND);
    float rmin = INFINITY;
    int nc = 0, ovf = 0;

    for (int ch = 0; ch < 32; ch++) {
        int buf = ch & 1;
        if (ch + 1 < 32) { stageB(smem, sb, ch + 1, buf ^ 1, tid); CP_COMMIT(); CP_WAIT1(); }
        else CP_WAIT0();
        __syncthreads();

        float acc[2][2][4];
        #pragma unroll
        for (int mt = 0; mt < 2; mt++)
            #pragma unroll
            for (int nt = 0; nt < 2; nt++)
                #pragma unroll
                for (int q = 0; q < 4; q++) acc[mt][nt][q] = 0.f;

        #pragma unroll
        for (int seg = 0; seg < 3; seg++) {
            uint32_t ab = a_off + (seg == 2 ? SA_LO : 0);
            uint32_t bb = b_off + buf * SB_BUF + (seg == 1 ? SB_HL : 0);
            #pragma unroll
            for (int kk = 0; kk < 16; kk++) {
                uint32_t A0[4], A1[4], B[4];
                ldsm4(A0, ab + kk * 32);
                ldsm4(A1, ab + kk * 32 + 16 * PITCH);
                ldsm4(B, bb + kk * 32);
                mma16816(acc[0][0], A0, B[0], B[1]);
                mma16816(acc[0][1], A0, B[2], B[3]);
                mma16816(acc[1][0], A1, B[0], B[1]);
                mma16816(acc[1][1], A1, B[2], B[3]);
            }
        }

        const float* en2s = (const float*)(smem + SEN2 + buf * 128);
        #pragma unroll
        for (int mt = 0; mt < 2; mt++) {
            #pragma unroll
            for (int nt = 0; nt < 2; nt++) {
                int cb = warp_n * 16 + nt * 8 + (lane & 3) * 2;
                float e0 = en2s[cb], e1 = en2s[cb + 1];
                #pragma unroll
                for (int half = 0; half < 2; half++) {
                    int r = warp_m * 32 + mt * 16 + half * 8 + (lane >> 2);
                    float2 dp;
                    dp.x = __fsub_rn(e0, 2.0f * acc[mt][nt][half * 2]);
                    dp.y = __fsub_rn(e1, 2.0f * acc[mt][nt][half * 2 + 1]);
                    *(float2*)&sd[r * 34 + cb] = dp;
                }
            }
        }
        __syncthreads();
        // per-row: branch-free chunk-min first; only scan-append when chunk can contribute
        if (tid < 128) {
            const float* rowd = &sd[tid * 34];
            float cmin = rowd[0];
            #pragma unroll
            for (int c = 1; c < 32; c++) cmin = fminf(cmin, rowd[c]);
            if (cmin < rmin + CAND_M) {
                #pragma unroll
                for (int c = 0; c < 32; c++) {
                    float a = rowd[c];
                    if (a < rmin + CAND_M) {
                        if (nc < NCAND) scand[tid * NCAND + nc] = (short)(ch * 32 + c);
                        else ovf = 1;
                        nc++;
                        if (a < rmin) rmin = a;
                    }
                }
            }
        }
        __syncthreads();
    }

    if (tid < 128) {
        int row = row0 + tid;
        if (ovf) {
            g_cnt[row] = -1;
            int p = atomicAdd(&g_nflag, 1);
            g_flag[p] = row;
        } else {
            g_cnt[row] = nc;
            for (int c = 0; c < nc; c++)
                g_cand[(size_t)row * NCAND + c] = scand[tid * NCAND + c];
        }
    }
}

// ---------------- k_cand: exact re-rank, float4 streams (order-preserving) ----------------
__global__ void k_cand(const float* __restrict__ z) {
    int warp = threadIdx.x >> 5, lane = threadIdx.x & 31;
    int row = blockIdx.x * 8 + warp;
    int cnt = g_cnt[row];
    if (cnt < 0) return;                       // overflow -> rescued
    int code = (lane < cnt) ? (int)g_cand[(size_t)row * NCAND + lane] : -1;
    float dist = INFINITY;
    if (lane < cnt) {
        const float4* zr4 = (const float4*)(z + ((size_t)row << 8));
        const float4* er4 = (const float4*)(g_eT + ((size_t)code << 8));
        float t = 0.f;
        #pragma unroll 8
        for (int q = 0; q < 64; q++) {
            float4 a = zr4[q], b = er4[q];
            t = fmaf(a.x, b.x, t);
            t = fmaf(a.y, b.y, t);
            t = fmaf(a.z, b.z, t);
            t = fmaf(a.w, b.w, t);
        }
        dist = __fsub_rn(__fadd_rn(g_zn2[row], g_en2[code]), 2.0f * t);
    }
    int ord = lane, bc = code;
    float bv = dist;
    #pragma unroll
    for (int off = 16; off; off >>= 1) {
        float ov = __shfl_xor_sync(0xffffffffu, bv, off);
        int oo = __shfl_xor_sync(0xffffffffu, ord, off);
        int oc = __shfl_xor_sync(0xffffffffu, bc, off);
        if (ov < bv || (ov == bv && oo < ord)) { bv = ov; ord = oo; bc = oc; }
    }
    if (lane == 0) g_idx[row] = bc;
}

// ---------------- block-batched exact rescue (overflow rows) ----------------
#define RSP 260
#define RS_SMEM ((32*RSP + 64*RSP + 256 + 256) * 4)

__global__ __launch_bounds__(256, 1)
void k_rescue(const float* __restrict__ z) {
    extern __shared__ float rs[];
    float* sz = rs;
    float* se = rs + 32 * RSP;
    float* mbv = se + 64 * RSP;
    int*   mbi = (int*)(mbv + 256);
    int tid = threadIdx.x;
    int r = tid >> 3, cs = tid & 7;
    int n = g_nflag;

    for (int base = blockIdx.x * 32; base < n; base += gridDim.x * 32) {
        int cnt = min(32, n - base);
        for (int i = tid; i < cnt * 64; i += 256) {
            int rr = i >> 6, q = (i & 63) << 2;
            int row = g_flag[base + rr];
            float4 vv = *(const float4*)&z[((size_t)row << 8) + q];
            sz[rr * RSP + q] = vv.x; sz[rr * RSP + q + 1] = vv.y;
            sz[rr * RSP + q + 2] = vv.z; sz[rr * RSP + q + 3] = vv.w;
        }
        float myzn2 = (r < cnt) ? g_zn2[g_flag[base + r]] : 0.f;
        float bv = INFINITY; int bi = 0;
        for (int cc = 0; cc < 16; cc++) {
            __syncthreads();
            for (int i = tid; i < 64 * 64; i += 256) {
                int c = i >> 6, q = (i & 63) << 2;
                float4 vv = *(const float4*)&g_eT[((size_t)(cc * 64 + c) << 8) + q];
                se[c * RSP + q] = vv.x; se[c * RSP + q + 1] = vv.y;
                se[c * RSP + q + 2] = vv.z; se[c * RSP + q + 3] = vv.w;
            }
            __syncthreads();
            if (r < cnt) {
                #pragma unroll
                for (int m = 0; m < 8; m++) {
                    int c = cs + 8 * m;
                    float t = 0.f;
                    #pragma unroll 8
                    for (int d = 0; d < 256; d++)
                        t = fmaf(sz[r * RSP + d], se[c * RSP + d], t);
                    int cde = cc * 64 + c;
                    float dist = __fsub_rn(__fadd_rn(myzn2, g_en2[cde]), 2.0f * t);
                    if (dist < bv) { bv = dist; bi = cde; }
                }
            }
        }
        mbv[tid] = bv; mbi[tid] = bi;
        __syncthreads();
        if (tid < cnt) {
            float fb = mbv[tid * 8]; int fi = mbi[tid * 8];
            #pragma unroll
            for (int s2 = 1; s2 < 8; s2++) {
                float vv = mbv[tid * 8 + s2]; int ii = mbi[tid * 8 + s2];
                if (vv < fb || (vv == fb && ii < fi)) { fb = vv; fi = ii; }
            }
            g_idx[g_flag[base + tid]] = fi;
        }
        __syncthreads();
    }
}

// ---------------- sampled exact index checker (256 rows) ----------------
__global__ void k_check(const float* __restrict__ z, const float* __restrict__ e) {
    __shared__ float srow[8][256];
    int warp = threadIdx.x >> 5, lane = threadIdx.x & 31;
    int row = (blockIdx.x * 8 + warp) * 256 + 128;
    for (int d = lane; d < 256; d += 32) srow[warp][d] = z[((size_t)row << 8) + d];
    __syncwarp();
    float zn2 = g_zn2[row];
    float bv = INFINITY; int bi = 0;
    for (int c = 0; c < 32; c++) {
        int code = c * 32 + lane;
        float t = 0.f;
        #pragma unroll 8
        for (int d = 0; d < 256; d++)
            t = fmaf(srow[warp][d], e[d * K + code], t);
        float dist = __fsub_rn(__fadd_rn(zn2, g_en2[code]), 2.0f * t);
        if (dist < bv) { bv = dist; bi = code; }
    }
    #pragma unroll
    for (int off = 16; off; off >>= 1) {
        float ov = __shfl_xor_sync(0xffffffffu, bv, off);
        int oi = __shfl_xor_sync(0xffffffffu, bi, off);
        if (ov < bv || (ov == bv && oi < bi)) { bv = ov; bi = oi; }
    }
    if (lane == 0 && g_idx[row] != bi) atomicAdd(&g_bad, 1);
}

// ---------------- conditional FFMA2 fp32 fallback (R6, bit-exact) ----------------
#define BM 128
#define BN 128
#define BK 16
#define TM 8
#define TN 8
#define BMP 132

__global__ __launch_bounds__(256, 2)
void k_fallback(const float* __restrict__ z, const float* __restrict__ e) {
    if (g_bad == 0) return;
    __shared__ float s_zT[BK][BMP];
    __shared__ float s_e[BK][BN];
    __shared__ float s_en2[BN];
    __shared__ float m_v[BM][16];
    __shared__ int   m_i[BM][16];

    int tid = threadIdx.x;
    int tx = tid & 15, ty = tid >> 4;
    int row0 = blockIdx.x * BM;

    float bestv[TM]; int besti[TM]; float my_zn2[TM];
    #pragma unroll
    for (int i = 0; i < TM; i++) {
        bestv[i] = INFINITY; besti[i] = 0;
        my_zn2[i] = g_zn2[row0 + ty * TM + i];
    }

    for (int kc = 0; kc < K; kc += BN) {
        __syncthreads();
        if (tid < BN) s_en2[tid] = g_en2[kc + tid];
        unsigned long long acc2[TM][TN / 2];
        #pragma unroll
        for (int i = 0; i < TM; i++)
            #pragma unroll
            for (int j = 0; j < TN / 2; j++) acc2[i][j] = 0ULL;
        for (int dk = 0; dk < D; dk += BK) {
            #pragma unroll
            for (int i = 0; i < 8; i++) {
                int l = i * 256 + tid;
                int r = l >> 4, d = l & 15;
                s_zT[d][r] = z[(size_t)(row0 + r) * D + dk + d];
                int d2 = l >> 7, k2 = l & 127;
                s_e[d2][k2] = e[(dk + d2) * K + kc + k2];
            }
            __syncthreads();
            #pragma unroll
            for (int d = 0; d < BK; d++) {
                float a[TM];
                float4 a0 = *(const float4*)&s_zT[d][ty * TM];
                float4 a1 = *(const float4*)&s_zT[d][ty * TM + 4];
                a[0]=a0.x; a[1]=a0.y; a[2]=a0.z; a[3]=a0.w;
                a[4]=a1.x; a[5]=a1.y; a[6]=a1.z; a[7]=a1.w;
                union { float4 v; unsigned long long u[2]; } bu0, bu1;
                bu0.v = *(const float4*)&s_e[d][tx * TN];
                bu1.v = *(const float4*)&s_e[d][tx * TN + 4];
                unsigned long long b2v[4] = { bu0.u[0], bu0.u[1], bu1.u[0], bu1.u[1] };
                #pragma unroll
                for (int i = 0; i < TM; i++) {
                    unsigned long long a2 = pack2(a[i]);
                    fma2(acc2[i][0], a2, b2v[0]);
                    fma2(acc2[i][1], a2, b2v[1]);
                    fma2(acc2[i][2], a2, b2v[2]);
                    fma2(acc2[i][3], a2, b2v[3]);
                }
            }
            __syncthreads();
        }
        #pragma unroll
        for (int i = 0; i < TM; i++) {
            #pragma unroll
            for (int j2 = 0; j2 < TN / 2; j2++) {
                float t0, t1;
                unpack2(t0, t1, acc2[i][j2]);
                int j = 2 * j2;
                float dist0 = __fsub_rn(__fadd_rn(my_zn2[i], s_en2[tx * TN + j]), 2.0f * t0);
                float dist1 = __fsub_rn(__fadd_rn(my_zn2[i], s_en2[tx * TN + j + 1]), 2.0f * t1);
                int code = kc + tx * TN + j;
                if (dist0 < bestv[i]) { bestv[i] = dist0; besti[i] = code; }
                if (dist1 < bestv[i]) { bestv[i] = dist1; besti[i] = code + 1; }
            }
        }
    }
    __syncthreads();
    #pragma unroll
    for (int i = 0; i < TM; i++) {
        m_v[ty * TM + i][tx] = bestv[i];
        m_i[ty * TM + i][tx] = besti[i];
    }
    __syncthreads();
    if (tid < BM) {
        float bv = m_v[tid][0]; int bi = m_i[tid][0];
        #pragma unroll
        for (int t = 1; t < 16; t++) {
            float v = m_v[tid][t]; int ii = m_i[tid][t];
            if (v < bv || (v == bv && ii < bi)) { bv = v; bi = ii; }
        }
        g_idx[row0 + tid] = bi;
    }
}

// ---------------- gather + losses ----------------
__global__ void k_gather(const float* __restrict__ z, float* __restrict__ out) {
    int warp = threadIdx.x >> 5, lane = threadIdx.x & 31;
    int row = blockIdx.x * 8 + warp;
    int k = g_idx[row];
    if (lane == 0) {
        atomicAdd(&g_hist[k], 1);
        out[QSIZE + row] = (float)k;
    }
    const float* er = &g_eT[k * D];
    const float* zr = z + (size_t)row * D;
    float* qr = out + (size_t)row * D;
    float ss = 0.f;
    #pragma unroll
    for (int d = lane; d < D; d += 32) {
        float q = er[d];
        float zv = zr[d];
        float diff = q - zv;
        ss = fmaf(diff, diff, ss);
        qr[d] = __fadd_rn(zv, __fsub_rn(q, zv));
    }
    #pragma unroll
    for (int off = 16; off; off >>= 1)
        ss += __shfl_xor_sync(0xffffffffu, ss, off);
    __shared__ float wsum[8];
    if (lane == 0) wsum[warp] = ss;
    __syncthreads();
    if (threadIdx.x == 0) {
        float t = 0.f;
        for (int w = 0; w < 8; w++) t += wsum[w];
        g_part[blockIdx.x] = t;
    }
}

__global__ void k_final(float* __restrict__ out) {
    __shared__ double sd2[256];
    int t = threadIdx.x;
    double s = 0.0;
    for (int i = t; i < 8192; i += 256) s += (double)g_part[i];
    sd2[t] = s;
    __syncthreads();
    for (int off = 128; off; off >>= 1) {
        if (t < off) sd2[t] += sd2[t + off];
        __syncthreads();
    }
    if (t == 0) {
        float vq = (float)(sd2[0] / (double)QSIZE);
        out[QSIZE + NROWS + 0] = vq;
        out[QSIZE + NROWS + 1] = 0.25f * vq;
        float ent = 0.f;
        for (int i = 0; i < K; i++) {
            float p = __fmul_rn((float)g_hist[i], 1.0f / 65536.0f);
            ent = __fadd_rn(ent, __fmul_rn(p, logf(__fadd_rn(p, 1e-10f))));
        }
        out[QSIZE + NROWS + 2] = expf(-ent);
    }
}

extern "C" void kernel_launch(void* const* d_in, const int* in_sizes, int n_in,
                              void* d_out, int out_size) {
    const float* z = (const float*)d_in[0];
    const float* e = (const float*)d_in[1];
    float* out = (float*)d_out;

    cudaFuncSetAttribute(k_phaseA, cudaFuncAttributeMaxDynamicSharedMemorySize, SMEM_TOT);
    cudaFuncSetAttribute(k_rescue, cudaFuncAttributeMaxDynamicSharedMemorySize, RS_SMEM);

    k_setup<<<2052, 256>>>(z, e);                          // idx 0: hist/flags + en2 + zn2
    k_prep<<<dim3(K / 32, D / 32), dim3(32, 8)>>>(e);      // idx 1
    k_phaseA<<<NROWS / 128, 256, SMEM_TOT>>>(z);           // idx 2
    k_cand<<<NROWS / 8, 256>>>(z);                         // idx 3  <- PROFILED
    k_rescue<<<256, 256, RS_SMEM>>>(z);                    // idx 4
    k_check<<<32, 256>>>(z, e);                            // idx 5
    k_fallback<<<NROWS / BM, 256>>>(z, e);                 // idx 6
    k_gather<<<NROWS / 8, 256>>>(z, out);                  // idx 7
    k_final<<<1, 256>>>(out);                              // idx 8
}

// round 14
// speedup vs baseline: 1.1976x; 1.1504x over previous
#include <cuda_runtime.h>
#include <cuda_bf16.h>
#include <math.h>
#include <stdint.h>

#define NROWS 65536
#define D 256
#define K 1024
#define QSIZE (NROWS*D)
#define CAND_M 6e-4f
#define NCAND 32

// ---------------- scratch ----------------
__device__ __align__(128) float g_eT[K*D];
__device__ __align__(128) float g_en2[K];
__device__ __align__(128) float g_zn2[NROWS];
__device__ int   g_idx[NROWS];
__device__ float g_part[8192];
__device__ int   g_hist[K];
__device__ __align__(128) __nv_bfloat16 g_ebh[K*D];   // bf16(e^T)
__device__ int   g_flag[NROWS];
__device__ int   g_nflag;
__device__ int   g_bad;
__device__ short g_cand[(size_t)NROWS*NCAND];
__device__ int   g_cnt[NROWS];

// ---------------- asm helpers ----------------
__device__ __forceinline__ uint32_t smem_u32(const void* p) {
    uint32_t a;
    asm("{ .reg .u64 t; cvta.to.shared.u64 t, %1; cvt.u32.u64 %0, t; }" : "=r"(a) : "l"(p));
    return a;
}
__device__ __forceinline__ void ldsm4(uint32_t* r, uint32_t addr) {
    asm volatile("ldmatrix.sync.aligned.m8n8.x4.shared.b16 {%0,%1,%2,%3}, [%4];"
        : "=r"(r[0]), "=r"(r[1]), "=r"(r[2]), "=r"(r[3]) : "r"(addr));
}
__device__ __forceinline__ void mma16816(float* c, const uint32_t* a, uint32_t b0, uint32_t b1) {
    asm volatile("mma.sync.aligned.m16n8k16.row.col.f32.bf16.bf16.f32 "
        "{%0,%1,%2,%3}, {%4,%5,%6,%7}, {%8,%9}, {%0,%1,%2,%3};"
        : "+f"(c[0]), "+f"(c[1]), "+f"(c[2]), "+f"(c[3])
        : "r"(a[0]), "r"(a[1]), "r"(a[2]), "r"(a[3]), "r"(b0), "r"(b1));
}
__device__ __forceinline__ void cp16(uint32_t dst, const void* src) {
    asm volatile("cp.async.cg.shared.global [%0], [%1], 16;" :: "r"(dst), "l"(src) : "memory");
}
#define CP_COMMIT() asm volatile("cp.async.commit_group;" ::: "memory")
#define CP_WAIT1()  asm volatile("cp.async.wait_group 1;" ::: "memory")
#define CP_WAIT0()  asm volatile("cp.async.wait_group 0;" ::: "memory")

__device__ __forceinline__ void fma2(unsigned long long& acc,
                                     unsigned long long a, unsigned long long b) {
    asm("fma.rn.f32x2 %0, %1, %2, %0;" : "+l"(acc) : "l"(a), "l"(b));
}
__device__ __forceinline__ unsigned long long pack2(float x) {
    unsigned long long r;
    asm("mov.b64 %0, {%1, %2};" : "=l"(r) : "f"(x), "f"(x));
    return r;
}
__device__ __forceinline__ void unpack2(float& lo, float& hi, unsigned long long v) {
    asm("mov.b64 {%0, %1}, %2;" : "=f"(lo), "=f"(hi) : "l"(v));
}

// ---------------- small kernels ----------------
__global__ void k_init_en2(const float* __restrict__ e) {
    int t = blockIdx.x * blockDim.x + threadIdx.x;
    if (t == 0) { g_nflag = 0; g_bad = 0; }
    if (t >= K) return;
    g_hist[t] = 0;
    float s = 0.f;
    for (int d = 0; d < D; ++d) {
        float v = e[d * K + t];
        s = __fadd_rn(s, __fmul_rn(v, v));
    }
    g_en2[t] = s;
}

__global__ void k_zn2(const float* __restrict__ z) {
    __shared__ float sz[32][257];
    int row0 = blockIdx.x * 32;
    int tid = threadIdx.x;
    #pragma unroll
    for (int i = 0; i < 32; i++) {
        int l = i * 256 + tid;
        int r = l >> 8, d = l & 255;
        sz[r][d] = z[(size_t)(row0 + r) * D + d];
    }
    __syncthreads();
    if (tid < 32) {
        float s = 0.f;
        for (int d = 0; d < D; ++d) {
            float v = sz[tid][d];
            s = __fadd_rn(s, __fmul_rn(v, v));
        }
        g_zn2[row0 + tid] = s;
    }
}

__global__ void k_prep(const float* __restrict__ e) {
    __shared__ float t[32][33];
    int kb = blockIdx.x * 32, db = blockIdx.y * 32;
    int tx = threadIdx.x, ty = threadIdx.y;
    #pragma unroll
    for (int i = 0; i < 32; i += 8)
        t[ty + i][tx] = e[(db + ty + i) * K + kb + tx];
    __syncthreads();
    #pragma unroll
    for (int i = 0; i < 32; i += 8) {
        float v = t[tx][ty + i];
        int off = (kb + ty + i) * D + db + tx;
        g_eT[off] = v;
        g_ebh[off] = __float2bfloat16_rn(v);
    }
}

// ---------------- phaseA: single-product bf16 HMMA + candidate generation ----------------
#define PITCH 528
#define SB_OFF 67584                     // 128*528 (A tile)
#define SB_BUF 16896                     // 32*528
#define SEN2   101376                    // SB_OFF + 2*SB_BUF
#define SDIST  101632                    // 128 x 34 floats
#define SCAND  119040                    // 128 x 32 shorts = 8192
#define SMEM_TOT 127232

__device__ __forceinline__ void stageB(char* smem, uint32_t sb, int chunk, int buf, int tid) {
    #pragma unroll
    for (int i = 0; i < 4; i++) {
        int lin = i * 256 + tid;          // 0..1023
        int r = lin >> 5, s = lin & 31;
        const __nv_bfloat16* src = g_ebh + ((size_t)(chunk * 32 + r) << 8) + (s << 3);
        uint32_t dst = sb + SB_OFF + buf * SB_BUF + r * PITCH + (s << 4);
        cp16(dst, src);
    }
    if (tid < 32)
        *(float*)(smem + SEN2 + buf * 128 + tid * 4) = g_en2[chunk * 32 + tid];
}

__global__ __launch_bounds__(256, 1)
void k_phaseA(const float* __restrict__ z) {
    extern __shared__ char smem[];
    uint32_t sb = smem_u32(smem);
    int tid = threadIdx.x, lane = tid & 31, wid = tid >> 5;
    int warp_m = wid >> 1, warp_n = wid & 1;
    int row0 = blockIdx.x * 128;

    // stage A tile: z rows -> bf16, row-major PITCH
    #pragma unroll 4
    for (int i = 0; i < 32; i++) {
        int gi = i * 256 + tid;
        int r = gi >> 6, c4 = (gi & 63) << 2;
        const float4 v = *(const float4*)(z + ((size_t)(row0 + r) << 8) + c4);
        __nv_bfloat16 h0 = __float2bfloat16_rn(v.x), h1 = __float2bfloat16_rn(v.y);
        __nv_bfloat16 h2 = __float2bfloat16_rn(v.z), h3 = __float2bfloat16_rn(v.w);
        uint2 hw;
        hw.x = (uint32_t)__bfloat16_as_ushort(h0) | ((uint32_t)__bfloat16_as_ushort(h1) << 16);
        hw.y = (uint32_t)__bfloat16_as_ushort(h2) | ((uint32_t)__bfloat16_as_ushort(h3) << 16);
        *(uint2*)(smem + r * PITCH + (c4 << 1)) = hw;
    }
    stageB(smem, sb, 0, 0, tid);
    CP_COMMIT();

    uint32_t a_off = sb + (uint32_t)(warp_m * 32 + (lane & 15)) * PITCH + ((lane >> 4) << 4);
    uint32_t b_off = sb + SB_OFF
        + (uint32_t)(warp_n * 16 + (lane & 7) + ((lane >> 4) << 3)) * PITCH
        + (((lane >> 3) & 1) << 4);

    float* sd = (float*)(smem + SDIST);
    short* scand = (short*)(smem + SCAND);
    float rmin = INFINITY;
    int nc = 0, ovf = 0;

    for (int ch = 0; ch < 32; ch++) {
        int buf = ch & 1;
        if (ch + 1 < 32) { stageB(smem, sb, ch + 1, buf ^ 1, tid); CP_COMMIT(); CP_WAIT1(); }
        else CP_WAIT0();
        __syncthreads();

        float acc[2][2][4];
        #pragma unroll
        for (int mt = 0; mt < 2; mt++)
            #pragma unroll
            for (int nt = 0; nt < 2; nt++)
                #pragma unroll
                for (int q = 0; q < 4; q++) acc[mt][nt][q] = 0.f;

        uint32_t bb = b_off + buf * SB_BUF;
        #pragma unroll
        for (int kk = 0; kk < 16; kk++) {
            uint32_t A0[4], A1[4], B[4];
            ldsm4(A0, a_off + kk * 32);
            ldsm4(A1, a_off + kk * 32 + 16 * PITCH);
            ldsm4(B, bb + kk * 32);
            mma16816(acc[0][0], A0, B[0], B[1]);
            mma16816(acc[0][1], A0, B[2], B[3]);
            mma16816(acc[1][0], A1, B[0], B[1]);
            mma16816(acc[1][1], A1, B[2], B[3]);
        }

        const float* en2s = (const float*)(smem + SEN2 + buf * 128);
        #pragma unroll
        for (int mt = 0; mt < 2; mt++) {
            #pragma unroll
            for (int nt = 0; nt < 2; nt++) {
                int cb = warp_n * 16 + nt * 8 + (lane & 3) * 2;
                float e0 = en2s[cb], e1 = en2s[cb + 1];
                #pragma unroll
                for (int half = 0; half < 2; half++) {
                    int r = warp_m * 32 + mt * 16 + half * 8 + (lane >> 2);
                    float2 dp;
                    dp.x = __fsub_rn(e0, 2.0f * acc[mt][nt][half * 2]);
                    dp.y = __fsub_rn(e1, 2.0f * acc[mt][nt][half * 2 + 1]);
                    *(float2*)&sd[r * 34 + cb] = dp;
                }
            }
        }
        __syncthreads();
        // per-row: chunk-min first, then append vs (min(rmin, cmin) + M) -- minimal inflation
        if (tid < 128) {
            const float* rowd = &sd[tid * 34];
            float cmin = rowd[0];
            #pragma unroll
            for (int c = 1; c < 32; c++) cmin = fminf(cmin, rowd[c]);
            if (cmin < rmin + CAND_M) {
                float thr = fminf(rmin, cmin) + CAND_M;
                #pragma unroll
                for (int c = 0; c < 32; c++) {
                    if (rowd[c] < thr) {
                        if (nc < NCAND) scand[tid * NCAND + nc] = (short)(ch * 32 + c);
                        else ovf = 1;
                        nc++;
                    }
                }
            }
            rmin = fminf(rmin, cmin);
        }
        __syncthreads();
    }

    if (tid < 128) {
        int row = row0 + tid;
        if (ovf) {
            g_cnt[row] = -1;
            int p = atomicAdd(&g_nflag, 1);
            g_flag[p] = row;
        } else {
            g_cnt[row] = nc;
            for (int c = 0; c < nc; c++)
                g_cand[(size_t)row * NCAND + c] = scand[tid * NCAND + c];
        }
    }
}

// ---------------- k_cand: exact re-rank, float4 streams (order-preserving) ----------------
__global__ void k_cand(const float* __restrict__ z) {
    int warp = threadIdx.x >> 5, lane = threadIdx.x & 31;
    int row = blockIdx.x * 8 + warp;
    int cnt = g_cnt[row];
    if (cnt < 0) return;                       // overflow -> rescued
    int code = (lane < cnt) ? (int)g_cand[(size_t)row * NCAND + lane] : -1;
    float dist = INFINITY;
    if (lane < cnt) {
        const float4* zr4 = (const float4*)(z + ((size_t)row << 8));
        const float4* er4 = (const float4*)(g_eT + ((size_t)code << 8));
        float t = 0.f;
        #pragma unroll 8
        for (int q = 0; q < 64; q++) {
            float4 a = zr4[q], b = er4[q];
            t = fmaf(a.x, b.x, t);
            t = fmaf(a.y, b.y, t);
            t = fmaf(a.z, b.z, t);
            t = fmaf(a.w, b.w, t);
        }
        dist = __fsub_rn(__fadd_rn(g_zn2[row], g_en2[code]), 2.0f * t);
    }
    int ord = lane, bc = code;
    float bv = dist;
    #pragma unroll
    for (int off = 16; off; off >>= 1) {
        float ov = __shfl_xor_sync(0xffffffffu, bv, off);
        int oo = __shfl_xor_sync(0xffffffffu, ord, off);
        int oc = __shfl_xor_sync(0xffffffffu, bc, off);
        if (ov < bv || (ov == bv && oo < ord)) { bv = ov; ord = oo; bc = oc; }
    }
    if (lane == 0) g_idx[row] = bc;
}

// ---------------- block-batched exact rescue (overflow rows) ----------------
#define RSP 260
#define RS_SMEM ((32*RSP + 64*RSP + 256 + 256) * 4)

__global__ __launch_bounds__(256, 1)
void k_rescue(const float* __restrict__ z) {
    extern __shared__ float rs[];
    float* sz = rs;
    float* se = rs + 32 * RSP;
    float* mbv = se + 64 * RSP;
    int*   mbi = (int*)(mbv + 256);
    int tid = threadIdx.x;
    int r = tid >> 3, cs = tid & 7;
    int n = g_nflag;

    for (int base = blockIdx.x * 32; base < n; base += gridDim.x * 32) {
        int cnt = min(32, n - base);
        for (int i = tid; i < cnt * 64; i += 256) {
            int rr = i >> 6, q = (i & 63) << 2;
            int row = g_flag[base + rr];
            float4 vv = *(const float4*)&z[((size_t)row << 8) + q];
            sz[rr * RSP + q] = vv.x; sz[rr * RSP + q + 1] = vv.y;
            sz[rr * RSP + q + 2] = vv.z; sz[rr * RSP + q + 3] = vv.w;
        }
        float myzn2 = (r < cnt) ? g_zn2[g_flag[base + r]] : 0.f;
        float bv = INFINITY; int bi = 0;
        for (int cc = 0; cc < 16; cc++) {
            __syncthreads();
            for (int i = tid; i < 64 * 64; i += 256) {
                int c = i >> 6, q = (i & 63) << 2;
                float4 vv = *(const float4*)&g_eT[((size_t)(cc * 64 + c) << 8) + q];
                se[c * RSP + q] = vv.x; se[c * RSP + q + 1] = vv.y;
                se[c * RSP + q + 2] = vv.z; se[c * RSP + q + 3] = vv.w;
            }
            __syncthreads();
            if (r < cnt) {
                #pragma unroll
                for (int m = 0; m < 8; m++) {
                    int c = cs + 8 * m;
                    float t = 0.f;
                    #pragma unroll 8
                    for (int d = 0; d < 256; d++)
                        t = fmaf(sz[r * RSP + d], se[c * RSP + d], t);
                    int cde = cc * 64 + c;
                    float dist = __fsub_rn(__fadd_rn(myzn2, g_en2[cde]), 2.0f * t);
                    if (dist < bv) { bv = dist; bi = cde; }
                }
            }
        }
        mbv[tid] = bv; mbi[tid] = bi;
        __syncthreads();
        if (tid < cnt) {
            float fb = mbv[tid * 8]; int fi = mbi[tid * 8];
            #pragma unroll
            for (int s2 = 1; s2 < 8; s2++) {
                float vv = mbv[tid * 8 + s2]; int ii = mbi[tid * 8 + s2];
                if (vv < fb || (vv == fb && ii < fi)) { fb = vv; fi = ii; }
            }
            g_idx[g_flag[base + tid]] = fi;
        }
        __syncthreads();
    }
}

// ---------------- sampled exact index checker (256 rows) ----------------
__global__ void k_check(const float* __restrict__ z, const float* __restrict__ e) {
    __shared__ float srow[8][256];
    int warp = threadIdx.x >> 5, lane = threadIdx.x & 31;
    int row = (blockIdx.x * 8 + warp) * 256 + 128;
    for (int d = lane; d < 256; d += 32) srow[warp][d] = z[((size_t)row << 8) + d];
    __syncwarp();
    float zn2 = g_zn2[row];
    float bv = INFINITY; int bi = 0;
    for (int c = 0; c < 32; c++) {
        int code = c * 32 + lane;
        float t = 0.f;
        #pragma unroll 8
        for (int d = 0; d < 256; d++)
            t = fmaf(srow[warp][d], e[d * K + code], t);
        float dist = __fsub_rn(__fadd_rn(zn2, g_en2[code]), 2.0f * t);
        if (dist < bv) { bv = dist; bi = code; }
    }
    #pragma unroll
    for (int off = 16; off; off >>= 1) {
        float ov = __shfl_xor_sync(0xffffffffu, bv, off);
        int oi = __shfl_xor_sync(0xffffffffu, bi, off);
        if (ov < bv || (ov == bv && oi < bi)) { bv = ov; bi = oi; }
    }
    if (lane == 0 && g_idx[row] != bi) atomicAdd(&g_bad, 1);
}

// ---------------- conditional FFMA2 fp32 fallback (R6, bit-exact) ----------------
#define BM 128
#define BN 128
#define BK 16
#define TM 8
#define TN 8
#define BMP 132

__global__ __launch_bounds__(256, 2)
void k_fallback(const float* __restrict__ z, const float* __restrict__ e) {
    if (g_bad == 0) return;
    __shared__ float s_zT[BK][BMP];
    __shared__ float s_e[BK][BN];
    __shared__ float s_en2[BN];
    __shared__ float m_v[BM][16];
    __shared__ int   m_i[BM][16];

    int tid = threadIdx.x;
    int tx = tid & 15, ty = tid >> 4;
    int row0 = blockIdx.x * BM;

    float bestv[TM]; int besti[TM]; float my_zn2[TM];
    #pragma unroll
    for (int i = 0; i < TM; i++) {
        bestv[i] = INFINITY; besti[i] = 0;
        my_zn2[i] = g_zn2[row0 + ty * TM + i];
    }

    for (int kc = 0; kc < K; kc += BN) {
        __syncthreads();
        if (tid < BN) s_en2[tid] = g_en2[kc + tid];
        unsigned long long acc2[TM][TN / 2];
        #pragma unroll
        for (int i = 0; i < TM; i++)
            #pragma unroll
            for (int j = 0; j < TN / 2; j++) acc2[i][j] = 0ULL;
        for (int dk = 0; dk < D; dk += BK) {
            #pragma unroll
            for (int i = 0; i < 8; i++) {
                int l = i * 256 + tid;
                int r = l >> 4, d = l & 15;
                s_zT[d][r] = z[(size_t)(row0 + r) * D + dk + d];
                int d2 = l >> 7, k2 = l & 127;
                s_e[d2][k2] = e[(dk + d2) * K + kc + k2];
            }
            __syncthreads();
            #pragma unroll
            for (int d = 0; d < BK; d++) {
                float a[TM];
                float4 a0 = *(const float4*)&s_zT[d][ty * TM];
                float4 a1 = *(const float4*)&s_zT[d][ty * TM + 4];
                a[0]=a0.x; a[1]=a0.y; a[2]=a0.z; a[3]=a0.w;
                a[4]=a1.x; a[5]=a1.y; a[6]=a1.z; a[7]=a1.w;
                union { float4 v; unsigned long long u[2]; } bu0, bu1;
                bu0.v = *(const float4*)&s_e[d][tx * TN];
                bu1.v = *(const float4*)&s_e[d][tx * TN + 4];
                unsigned long long b2v[4] = { bu0.u[0], bu0.u[1], bu1.u[0], bu1.u[1] };
                #pragma unroll
                for (int i = 0; i < TM; i++) {
                    unsigned long long a2 = pack2(a[i]);
                    fma2(acc2[i][0], a2, b2v[0]);
                    fma2(acc2[i][1], a2, b2v[1]);
                    fma2(acc2[i][2], a2, b2v[2]);
                    fma2(acc2[i][3], a2, b2v[3]);
                }
            }
            __syncthreads();
        }
        #pragma unroll
        for (int i = 0; i < TM; i++) {
            #pragma unroll
            for (int j2 = 0; j2 < TN / 2; j2++) {
                float t0, t1;
                unpack2(t0, t1, acc2[i][j2]);
                int j = 2 * j2;
                float dist0 = __fsub_rn(__fadd_rn(my_zn2[i], s_en2[tx * TN + j]), 2.0f * t0);
                float dist1 = __fsub_rn(__fadd_rn(my_zn2[i], s_en2[tx * TN + j + 1]), 2.0f * t1);
                int code = kc + tx * TN + j;
                if (dist0 < bestv[i]) { bestv[i] = dist0; besti[i] = code; }
                if (dist1 < bestv[i]) { bestv[i] = dist1; besti[i] = code + 1; }
            }
        }
    }
    __syncthreads();
    #pragma unroll
    for (int i = 0; i < TM; i++) {
        m_v[ty * TM + i][tx] = bestv[i];
        m_i[ty * TM + i][tx] = besti[i];
    }
    __syncthreads();
    if (tid < BM) {
        float bv = m_v[tid][0]; int bi = m_i[tid][0];
        #pragma unroll
        for (int t = 1; t < 16; t++) {
            float v = m_v[tid][t]; int ii = m_i[tid][t];
            if (v < bv || (v == bv && ii < bi)) { bv = v; bi = ii; }
        }
        g_idx[row0 + tid] = bi;
    }
}

// ---------------- gather + losses ----------------
__global__ void k_gather(const float* __restrict__ z, float* __restrict__ out) {
    int warp = threadIdx.x >> 5, lane = threadIdx.x & 31;
    int row = blockIdx.x * 8 + warp;
    int k = g_idx[row];
    if (lane == 0) {
        atomicAdd(&g_hist[k], 1);
        out[QSIZE + row] = (float)k;
    }
    const float* er = &g_eT[k * D];
    const float* zr = z + (size_t)row * D;
    float* qr = out + (size_t)row * D;
    float ss = 0.f;
    #pragma unroll
    for (int d = lane; d < D; d += 32) {
        float q = er[d];
        float zv = zr[d];
        float diff = q - zv;
        ss = fmaf(diff, diff, ss);
        qr[d] = __fadd_rn(zv, __fsub_rn(q, zv));
    }
    #pragma unroll
    for (int off = 16; off; off >>= 1)
        ss += __shfl_xor_sync(0xffffffffu, ss, off);
    __shared__ float wsum[8];
    if (lane == 0) wsum[warp] = ss;
    __syncthreads();
    if (threadIdx.x == 0) {
        float t = 0.f;
        for (int w = 0; w < 8; w++) t += wsum[w];
        g_part[blockIdx.x] = t;
    }
}

__global__ void k_final(float* __restrict__ out) {
    __shared__ double sd2[256];
    int t = threadIdx.x;
    double s = 0.0;
    for (int i = t; i < 8192; i += 256) s += (double)g_part[i];
    sd2[t] = s;
    __syncthreads();
    for (int off = 128; off; off >>= 1) {
        if (t < off) sd2[t] += sd2[t + off];
        __syncthreads();
    }
    if (t == 0) {
        float vq = (float)(sd2[0] / (double)QSIZE);
        out[QSIZE + NROWS + 0] = vq;
        out[QSIZE + NROWS + 1] = 0.25f * vq;
        float ent = 0.f;
        for (int i = 0; i < K; i++) {
            float p = __fmul_rn((float)g_hist[i], 1.0f / 65536.0f);
            ent = __fadd_rn(ent, __fmul_rn(p, logf(__fadd_rn(p, 1e-10f))));
        }
        out[QSIZE + NROWS + 2] = expf(-ent);
    }
}

extern "C" void kernel_launch(void* const* d_in, const int* in_sizes, int n_in,
                              void* d_out, int out_size) {
    const float* z = (const float*)d_in[0];
    const float* e = (const float*)d_in[1];
    float* out = (float*)d_out;

    cudaFuncSetAttribute(k_phaseA, cudaFuncAttributeMaxDynamicSharedMemorySize, SMEM_TOT);
    cudaFuncSetAttribute(k_rescue, cudaFuncAttributeMaxDynamicSharedMemorySize, RS_SMEM);

    k_init_en2<<<4, 256>>>(e);                             // idx 0
    k_zn2<<<NROWS / 32, 256>>>(z);                         // idx 1
    k_prep<<<dim3(K / 32, D / 32), dim3(32, 8)>>>(e);      // idx 2
    k_phaseA<<<NROWS / 128, 256, SMEM_TOT>>>(z);           // idx 3  <- PROFILED
    k_cand<<<NROWS / 8, 256>>>(z);                         // idx 4
    k_rescue<<<256, 256, RS_SMEM>>>(z);                    // idx 5
    k_check<<<32, 256>>>(z, e);                            // idx 6
    k_fallback<<<NROWS / BM, 256>>>(z, e);                 // idx 7
    k_gather<<<NROWS / 8, 256>>>(z, out);                  // idx 8
    k_final<<<1, 256>>>(out);                              // idx 9
}

// round 15
// speedup vs baseline: 1.9780x; 1.6517x over previous
#include <cuda_runtime.h>
#include <cuda_bf16.h>
#include <math.h>
#include <stdint.h>

#define NROWS 65536
#define D 256
#define K 1024
#define QSIZE (NROWS*D)
#define CAND_M 6e-4f
#define NCAND 64

// ---------------- scratch ----------------
__device__ __align__(128) float g_eT[K*D];
__device__ __align__(128) float g_en2[K];
__device__ __align__(128) float g_zn2[NROWS];
__device__ int   g_idx[NROWS];
__device__ float g_part[8192];
__device__ int   g_hist[K];
__device__ __align__(128) __nv_bfloat16 g_ebh[K*D];   // bf16(e^T)
__device__ int   g_flag[NROWS];
__device__ int   g_nflag;
__device__ int   g_bad;
__device__ short g_cand[(size_t)NROWS*NCAND];
__device__ int   g_cnt[NROWS];

// ---------------- asm helpers ----------------
__device__ __forceinline__ uint32_t smem_u32(const void* p) {
    uint32_t a;
    asm("{ .reg .u64 t; cvta.to.shared.u64 t, %1; cvt.u32.u64 %0, t; }" : "=r"(a) : "l"(p));
    return a;
}
__device__ __forceinline__ void ldsm4(uint32_t* r, uint32_t addr) {
    asm volatile("ldmatrix.sync.aligned.m8n8.x4.shared.b16 {%0,%1,%2,%3}, [%4];"
        : "=r"(r[0]), "=r"(r[1]), "=r"(r[2]), "=r"(r[3]) : "r"(addr));
}
__device__ __forceinline__ void mma16816(float* c, const uint32_t* a, uint32_t b0, uint32_t b1) {
    asm volatile("mma.sync.aligned.m16n8k16.row.col.f32.bf16.bf16.f32 "
        "{%0,%1,%2,%3}, {%4,%5,%6,%7}, {%8,%9}, {%0,%1,%2,%3};"
        : "+f"(c[0]), "+f"(c[1]), "+f"(c[2]), "+f"(c[3])
        : "r"(a[0]), "r"(a[1]), "r"(a[2]), "r"(a[3]), "r"(b0), "r"(b1));
}
__device__ __forceinline__ void cp16(uint32_t dst, const void* src) {
    asm volatile("cp.async.cg.shared.global [%0], [%1], 16;" :: "r"(dst), "l"(src) : "memory");
}
#define CP_COMMIT() asm volatile("cp.async.commit_group;" ::: "memory")
#define CP_WAIT1()  asm volatile("cp.async.wait_group 1;" ::: "memory")
#define CP_WAIT0()  asm volatile("cp.async.wait_group 0;" ::: "memory")

__device__ __forceinline__ void fma2(unsigned long long& acc,
                                     unsigned long long a, unsigned long long b) {
    asm("fma.rn.f32x2 %0, %1, %2, %0;" : "+l"(acc) : "l"(a), "l"(b));
}
__device__ __forceinline__ unsigned long long pack2(float x) {
    unsigned long long r;
    asm("mov.b64 %0, {%1, %2};" : "=l"(r) : "f"(x), "f"(x));
    return r;
}
__device__ __forceinline__ void unpack2(float& lo, float& hi, unsigned long long v) {
    asm("mov.b64 {%0, %1}, %2;" : "=f"(lo), "=f"(hi) : "l"(v));
}

// ---------------- merged setup: zn2 (2048) + en2/init (4) + prep (256) ----------------
__global__ void k_setup(const float* __restrict__ z, const float* __restrict__ e) {
    int b = blockIdx.x;
    int tid = threadIdx.x;
    if (b < 2048) {
        __shared__ float sz[32][257];
        int row0 = b * 32;
        #pragma unroll
        for (int i = 0; i < 32; i++) {
            int l = i * 256 + tid;
            int r = l >> 8, d = l & 255;
            sz[r][d] = z[(size_t)(row0 + r) * D + d];
        }
        __syncthreads();
        if (tid < 32) {
            float s = 0.f;
            for (int d = 0; d < D; ++d) {
                float v = sz[tid][d];
                s = __fadd_rn(s, __fmul_rn(v, v));
            }
            g_zn2[row0 + tid] = s;
        }
        return;
    }
    if (b < 2052) {
        int t = (b - 2048) * 256 + tid;
        if (t == 0) { g_nflag = 0; g_bad = 0; }
        if (t < K) {
            g_hist[t] = 0;
            float s = 0.f;
            for (int d = 0; d < D; ++d) {
                float v = e[d * K + t];
                s = __fadd_rn(s, __fmul_rn(v, v));
            }
            g_en2[t] = s;
        }
        return;
    }
    // prep: transpose + bf16 (block (b-2052) maps to kb, db)
    __shared__ float t[32][33];
    int bb = b - 2052;
    int kb = (bb & 31) * 32, db = (bb >> 5) * 32;
    int tx = tid & 31, ty = tid >> 5;    // 32 x 8
    #pragma unroll
    for (int i = 0; i < 32; i += 8)
        t[ty + i][tx] = e[(db + ty + i) * K + kb + tx];
    __syncthreads();
    #pragma unroll
    for (int i = 0; i < 32; i += 8) {
        float v = t[tx][ty + i];
        int off = (kb + ty + i) * D + db + tx;
        g_eT[off] = v;
        g_ebh[off] = __float2bfloat16_rn(v);
    }
}

// ---------------- phaseA: single-product bf16 HMMA + candidate generation ----------------
#define PITCH 528
#define SB_OFF 67584                     // 128*528 (A tile)
#define SB_BUF 16896                     // 32*528
#define SEN2   101376
#define SDIST  101632                    // 128 x 34 floats = 17408
#define SCAND  119040                    // 128 x 64 shorts = 16384
#define SMEM_TOT 135424

__device__ __forceinline__ void stageB(char* smem, uint32_t sb, int chunk, int buf, int tid) {
    #pragma unroll
    for (int i = 0; i < 4; i++) {
        int lin = i * 256 + tid;
        int r = lin >> 5, s = lin & 31;
        const __nv_bfloat16* src = g_ebh + ((size_t)(chunk * 32 + r) << 8) + (s << 3);
        uint32_t dst = sb + SB_OFF + buf * SB_BUF + r * PITCH + (s << 4);
        cp16(dst, src);
    }
    if (tid < 32)
        *(float*)(smem + SEN2 + buf * 128 + tid * 4) = g_en2[chunk * 32 + tid];
}

__global__ __launch_bounds__(256, 1)
void k_phaseA(const float* __restrict__ z) {
    extern __shared__ char smem[];
    uint32_t sb = smem_u32(smem);
    int tid = threadIdx.x, lane = tid & 31, wid = tid >> 5;
    int warp_m = wid >> 1, warp_n = wid & 1;
    int row0 = blockIdx.x * 128;

    #pragma unroll 4
    for (int i = 0; i < 32; i++) {
        int gi = i * 256 + tid;
        int r = gi >> 6, c4 = (gi & 63) << 2;
        const float4 v = *(const float4*)(z + ((size_t)(row0 + r) << 8) + c4);
        __nv_bfloat16 h0 = __float2bfloat16_rn(v.x), h1 = __float2bfloat16_rn(v.y);
        __nv_bfloat16 h2 = __float2bfloat16_rn(v.z), h3 = __float2bfloat16_rn(v.w);
        uint2 hw;
        hw.x = (uint32_t)__bfloat16_as_ushort(h0) | ((uint32_t)__bfloat16_as_ushort(h1) << 16);
        hw.y = (uint32_t)__bfloat16_as_ushort(h2) | ((uint32_t)__bfloat16_as_ushort(h3) << 16);
        *(uint2*)(smem + r * PITCH + (c4 << 1)) = hw;
    }
    stageB(smem, sb, 0, 0, tid);
    CP_COMMIT();

    uint32_t a_off = sb + (uint32_t)(warp_m * 32 + (lane & 15)) * PITCH + ((lane >> 4) << 4);
    uint32_t b_off = sb + SB_OFF
        + (uint32_t)(warp_n * 16 + (lane & 7) + ((lane >> 4) << 3)) * PITCH
        + (((lane >> 3) & 1) << 4);

    float* sd = (float*)(smem + SDIST);
    short* scand = (short*)(smem + SCAND);
    float rmin = INFINITY;
    int nc = 0, ovf = 0;

    for (int ch = 0; ch < 32; ch++) {
        int buf = ch & 1;
        if (ch + 1 < 32) { stageB(smem, sb, ch + 1, buf ^ 1, tid); CP_COMMIT(); CP_WAIT1(); }
        else CP_WAIT0();
        __syncthreads();

        float acc[2][2][4];
        #pragma unroll
        for (int mt = 0; mt < 2; mt++)
            #pragma unroll
            for (int nt = 0; nt < 2; nt++)
                #pragma unroll
                for (int q = 0; q < 4; q++) acc[mt][nt][q] = 0.f;

        uint32_t bb = b_off + buf * SB_BUF;
        #pragma unroll
        for (int kk = 0; kk < 16; kk++) {
            uint32_t A0[4], A1[4], B[4];
            ldsm4(A0, a_off + kk * 32);
            ldsm4(A1, a_off + kk * 32 + 16 * PITCH);
            ldsm4(B, bb + kk * 32);
            mma16816(acc[0][0], A0, B[0], B[1]);
            mma16816(acc[0][1], A0, B[2], B[3]);
            mma16816(acc[1][0], A1, B[0], B[1]);
            mma16816(acc[1][1], A1, B[2], B[3]);
        }

        const float* en2s = (const float*)(smem + SEN2 + buf * 128);
        #pragma unroll
        for (int mt = 0; mt < 2; mt++) {
            #pragma unroll
            for (int nt = 0; nt < 2; nt++) {
                int cb = warp_n * 16 + nt * 8 + (lane & 3) * 2;
                float e0 = en2s[cb], e1 = en2s[cb + 1];
                #pragma unroll
                for (int half = 0; half < 2; half++) {
                    int r = warp_m * 32 + mt * 16 + half * 8 + (lane >> 2);
                    float2 dp;
                    dp.x = __fsub_rn(e0, 2.0f * acc[mt][nt][half * 2]);
                    dp.y = __fsub_rn(e1, 2.0f * acc[mt][nt][half * 2 + 1]);
                    *(float2*)&sd[r * 34 + cb] = dp;
                }
            }
        }
        __syncthreads();
        if (tid < 128) {
            const float* rowd = &sd[tid * 34];
            float cmin = rowd[0];
            #pragma unroll
            for (int c = 1; c < 32; c++) cmin = fminf(cmin, rowd[c]);
            if (cmin < rmin + CAND_M) {
                float thr = fminf(rmin, cmin) + CAND_M;
                #pragma unroll
                for (int c = 0; c < 32; c++) {
                    if (rowd[c] < thr) {
                        if (nc < NCAND) scand[tid * NCAND + nc] = (short)(ch * 32 + c);
                        else ovf = 1;
                        nc++;
                    }
                }
            }
            rmin = fminf(rmin, cmin);
        }
        __syncthreads();
    }

    if (tid < 128) {
        int row = row0 + tid;
        if (ovf) {
            g_cnt[row] = -1;
            int p = atomicAdd(&g_nflag, 1);
            g_flag[p] = row;
        } else {
            g_cnt[row] = nc;
            for (int c = 0; c < nc; c++)
                g_cand[(size_t)row * NCAND + c] = scand[tid * NCAND + c];
        }
    }
}

// ---------------- k_cand: exact re-rank, float4 streams (order-preserving) ----------------
__global__ void k_cand(const float* __restrict__ z) {
    int warp = threadIdx.x >> 5, lane = threadIdx.x & 31;
    int row = blockIdx.x * 8 + warp;
    int cnt = g_cnt[row];
    if (cnt < 0) return;
    int code = (lane < cnt) ? (int)g_cand[(size_t)row * NCAND + lane] : -1;
    float dist = INFINITY;
    if (lane < cnt) {
        const float4* zr4 = (const float4*)(z + ((size_t)row << 8));
        const float4* er4 = (const float4*)(g_eT + ((size_t)code << 8));
        float t = 0.f;
        #pragma unroll 8
        for (int q = 0; q < 64; q++) {
            float4 a = zr4[q], b = er4[q];
            t = fmaf(a.x, b.x, t);
            t = fmaf(a.y, b.y, t);
            t = fmaf(a.z, b.z, t);
            t = fmaf(a.w, b.w, t);
        }
        dist = __fsub_rn(__fadd_rn(g_zn2[row], g_en2[code]), 2.0f * t);
    }
    int ord = lane, bc = code;
    float bv = dist;
    #pragma unroll
    for (int off = 16; off; off >>= 1) {
        float ov = __shfl_xor_sync(0xffffffffu, bv, off);
        int oo = __shfl_xor_sync(0xffffffffu, ord, off);
        int oc = __shfl_xor_sync(0xffffffffu, bc, off);
        if (ov < bv || (ov == bv && oo < ord)) { bv = ov; ord = oo; bc = oc; }
    }
    if (lane == 0) g_idx[row] = bc;
}

// ---------------- block-batched exact rescue (overflow rows; PROFILED slot) ----------------
#define RSP 260
#define RS_SMEM ((32*RSP + 64*RSP + 256 + 256) * 4)

__global__ __launch_bounds__(256, 1)
void k_rescue(const float* __restrict__ z) {
    extern __shared__ float rs[];
    float* sz = rs;
    float* se = rs + 32 * RSP;
    float* mbv = se + 64 * RSP;
    int*   mbi = (int*)(mbv + 256);
    int tid = threadIdx.x;
    int r = tid >> 3, cs = tid & 7;
    int n = g_nflag;

    for (int base = blockIdx.x * 32; base < n; base += gridDim.x * 32) {
        int cnt = min(32, n - base);
        for (int i = tid; i < cnt * 64; i += 256) {
            int rr = i >> 6, q = (i & 63) << 2;
            int row = g_flag[base + rr];
            float4 vv = *(const float4*)&z[((size_t)row << 8) + q];
            sz[rr * RSP + q] = vv.x; sz[rr * RSP + q + 1] = vv.y;
            sz[rr * RSP + q + 2] = vv.z; sz[rr * RSP + q + 3] = vv.w;
        }
        float myzn2 = (r < cnt) ? g_zn2[g_flag[base + r]] : 0.f;
        float bv = INFINITY; int bi = 0;
        for (int cc = 0; cc < 16; cc++) {
            __syncthreads();
            for (int i = tid; i < 64 * 64; i += 256) {
                int c = i >> 6, q = (i & 63) << 2;
                float4 vv = *(const float4*)&g_eT[((size_t)(cc * 64 + c) << 8) + q];
                se[c * RSP + q] = vv.x; se[c * RSP + q + 1] = vv.y;
                se[c * RSP + q + 2] = vv.z; se[c * RSP + q + 3] = vv.w;
            }
            __syncthreads();
            if (r < cnt) {
                #pragma unroll
                for (int m = 0; m < 8; m++) {
                    int c = cs + 8 * m;
                    float t = 0.f;
                    #pragma unroll 8
                    for (int d = 0; d < 256; d++)
                        t = fmaf(sz[r * RSP + d], se[c * RSP + d], t);
                    int cde = cc * 64 + c;
                    float dist = __fsub_rn(__fadd_rn(myzn2, g_en2[cde]), 2.0f * t);
                    if (dist < bv) { bv = dist; bi = cde; }
                }
            }
        }
        mbv[tid] = bv; mbi[tid] = bi;
        __syncthreads();
        if (tid < cnt) {
            float fb = mbv[tid * 8]; int fi = mbi[tid * 8];
            #pragma unroll
            for (int s2 = 1; s2 < 8; s2++) {
                float vv = mbv[tid * 8 + s2]; int ii = mbi[tid * 8 + s2];
                if (vv < fb || (vv == fb && ii < fi)) { fb = vv; fi = ii; }
            }
            g_idx[g_flag[base + tid]] = fi;
        }
        __syncthreads();
    }
}

// ---------------- parallel exact index checker (256 rows, block per row) ----------------
__global__ void k_check(const float* __restrict__ z, const float* __restrict__ e) {
    __shared__ float srow[256];
    __shared__ float rv[256];
    __shared__ int   ri[256];
    int tid = threadIdx.x;
    int row = blockIdx.x * 256 + 128;
    srow[tid] = z[((size_t)row << 8) + tid];
    __syncthreads();
    float zn2 = g_zn2[row];
    float bv = INFINITY; int bi = 0;
    #pragma unroll
    for (int j = 0; j < 4; j++) {
        int code = j * 256 + tid;
        float t = 0.f;
        #pragma unroll 8
        for (int d = 0; d < 256; d++)
            t = fmaf(srow[d], e[d * K + code], t);
        float dist = __fsub_rn(__fadd_rn(zn2, g_en2[code]), 2.0f * t);
        if (dist < bv) { bv = dist; bi = code; }
    }
    rv[tid] = bv; ri[tid] = bi;
    __syncthreads();
    for (int off = 128; off; off >>= 1) {
        if (tid < off) {
            float ov = rv[tid + off]; int oi = ri[tid + off];
            if (ov < rv[tid] || (ov == rv[tid] && oi < ri[tid])) { rv[tid] = ov; ri[tid] = oi; }
        }
        __syncthreads();
    }
    if (tid == 0 && g_idx[row] != ri[0]) atomicAdd(&g_bad, 1);
}

// ---------------- conditional FFMA2 fp32 fallback (R6, bit-exact) ----------------
#define BM 128
#define BN 128
#define BK 16
#define TM 8
#define TN 8
#define BMP 132

__global__ __launch_bounds__(256, 2)
void k_fallback(const float* __restrict__ z, const float* __restrict__ e) {
    if (g_bad == 0) return;
    __shared__ float s_zT[BK][BMP];
    __shared__ float s_e[BK][BN];
    __shared__ float s_en2[BN];
    __shared__ float m_v[BM][16];
    __shared__ int   m_i[BM][16];

    int tid = threadIdx.x;
    int tx = tid & 15, ty = tid >> 4;
    int row0 = blockIdx.x * BM;

    float bestv[TM]; int besti[TM]; float my_zn2[TM];
    #pragma unroll
    for (int i = 0; i < TM; i++) {
        bestv[i] = INFINITY; besti[i] = 0;
        my_zn2[i] = g_zn2[row0 + ty * TM + i];
    }

    for (int kc = 0; kc < K; kc += BN) {
        __syncthreads();
        if (tid < BN) s_en2[tid] = g_en2[kc + tid];
        unsigned long long acc2[TM][TN / 2];
        #pragma unroll
        for (int i = 0; i < TM; i++)
            #pragma unroll
            for (int j = 0; j < TN / 2; j++) acc2[i][j] = 0ULL;
        for (int dk = 0; dk < D; dk += BK) {
            #pragma unroll
            for (int i = 0; i < 8; i++) {
                int l = i * 256 + tid;
                int r = l >> 4, d = l & 15;
                s_zT[d][r] = z[(size_t)(row0 + r) * D + dk + d];
                int d2 = l >> 7, k2 = l & 127;
                s_e[d2][k2] = e[(dk + d2) * K + kc + k2];
            }
            __syncthreads();
            #pragma unroll
            for (int d = 0; d < BK; d++) {
                float a[TM];
                float4 a0 = *(const float4*)&s_zT[d][ty * TM];
                float4 a1 = *(const float4*)&s_zT[d][ty * TM + 4];
                a[0]=a0.x; a[1]=a0.y; a[2]=a0.z; a[3]=a0.w;
                a[4]=a1.x; a[5]=a1.y; a[6]=a1.z; a[7]=a1.w;
                union { float4 v; unsigned long long u[2]; } bu0, bu1;
                bu0.v = *(const float4*)&s_e[d][tx * TN];
                bu1.v = *(const float4*)&s_e[d][tx * TN + 4];
                unsigned long long b2v[4] = { bu0.u[0], bu0.u[1], bu1.u[0], bu1.u[1] };
                #pragma unroll
                for (int i = 0; i < TM; i++) {
                    unsigned long long a2 = pack2(a[i]);
                    fma2(acc2[i][0], a2, b2v[0]);
                    fma2(acc2[i][1], a2, b2v[1]);
                    fma2(acc2[i][2], a2, b2v[2]);
                    fma2(acc2[i][3], a2, b2v[3]);
                }
            }
            __syncthreads();
        }
        #pragma unroll
        for (int i = 0; i < TM; i++) {
            #pragma unroll
            for (int j2 = 0; j2 < TN / 2; j2++) {
                float t0, t1;
                unpack2(t0, t1, acc2[i][j2]);
                int j = 2 * j2;
                float dist0 = __fsub_rn(__fadd_rn(my_zn2[i], s_en2[tx * TN + j]), 2.0f * t0);
                float dist1 = __fsub_rn(__fadd_rn(my_zn2[i], s_en2[tx * TN + j + 1]), 2.0f * t1);
                int code = kc + tx * TN + j;
                if (dist0 < bestv[i]) { bestv[i] = dist0; besti[i] = code; }
                if (dist1 < bestv[i]) { bestv[i] = dist1; besti[i] = code + 1; }
            }
        }
    }
    __syncthreads();
    #pragma unroll
    for (int i = 0; i < TM; i++) {
        m_v[ty * TM + i][tx] = bestv[i];
        m_i[ty * TM + i][tx] = besti[i];
    }
    __syncthreads();
    if (tid < BM) {
        float bv = m_v[tid][0]; int bi = m_i[tid][0];
        #pragma unroll
        for (int t = 1; t < 16; t++) {
            float v = m_v[tid][t]; int ii = m_i[tid][t];
            if (v < bv || (v == bv && ii < bi)) { bv = v; bi = ii; }
        }
        g_idx[row0 + tid] = bi;
    }
}

// ---------------- gather + losses ----------------
__global__ void k_gather(const float* __restrict__ z, float* __restrict__ out) {
    int warp = threadIdx.x >> 5, lane = threadIdx.x & 31;
    int row = blockIdx.x * 8 + warp;
    int k = g_idx[row];
    if (lane == 0) {
        atomicAdd(&g_hist[k], 1);
        out[QSIZE + row] = (float)k;
    }
    const float* er = &g_eT[k * D];
    const float* zr = z + (size_t)row * D;
    float* qr = out + (size_t)row * D;
    float ss = 0.f;
    #pragma unroll
    for (int d = lane; d < D; d += 32) {
        float q = er[d];
        float zv = zr[d];
        float diff = q - zv;
        ss = fmaf(diff, diff, ss);
        qr[d] = __fadd_rn(zv, __fsub_rn(q, zv));
    }
    #pragma unroll
    for (int off = 16; off; off >>= 1)
        ss += __shfl_xor_sync(0xffffffffu, ss, off);
    __shared__ float wsum[8];
    if (lane == 0) wsum[warp] = ss;
    __syncthreads();
    if (threadIdx.x == 0) {
        float t = 0.f;
        for (int w = 0; w < 8; w++) t += wsum[w];
        g_part[blockIdx.x] = t;
    }
}

__global__ void k_final(float* __restrict__ out) {
    __shared__ double sd2[256];
    __shared__ float sent[256];
    int t = threadIdx.x;
    double s = 0.0;
    for (int i = t; i < 8192; i += 256) s += (double)g_part[i];
    sd2[t] = s;
    // entropy partials (4 codes per thread, ascending)
    float ep = 0.f;
    #pragma unroll
    for (int j = 0; j < 4; j++) {
        int i = t * 4 + j;
        float p = __fmul_rn((float)g_hist[i], 1.0f / 65536.0f);
        ep = __fadd_rn(ep, __fmul_rn(p, logf(__fadd_rn(p, 1e-10f))));
    }
    sent[t] = ep;
    __syncthreads();
    for (int off = 128; off; off >>= 1) {
        if (t < off) {
            sd2[t] += sd2[t + off];
            sent[t] = __fadd_rn(sent[t], sent[t + off]);
        }
        __syncthreads();
    }
    if (t == 0) {
        float vq = (float)(sd2[0] / (double)QSIZE);
        out[QSIZE + NROWS + 0] = vq;
        out[QSIZE + NROWS + 1] = 0.25f * vq;
        out[QSIZE + NROWS + 2] = expf(-sent[0]);
    }
}

extern "C" void kernel_launch(void* const* d_in, const int* in_sizes, int n_in,
                              void* d_out, int out_size) {
    const float* z = (const float*)d_in[0];
    const float* e = (const float*)d_in[1];
    float* out = (float*)d_out;

    cudaFuncSetAttribute(k_phaseA, cudaFuncAttributeMaxDynamicSharedMemorySize, SMEM_TOT);
    cudaFuncSetAttribute(k_rescue, cudaFuncAttributeMaxDynamicSharedMemorySize, RS_SMEM);

    k_setup<<<2308, 256>>>(z, e);                          // idx 0: zn2 + en2/init + prep
    k_phaseA<<<NROWS / 128, 256, SMEM_TOT>>>(z);           // idx 1
    k_cand<<<NROWS / 8, 256>>>(z);                         // idx 2
    k_rescue<<<256, 256, RS_SMEM>>>(z);                    // idx 3  <- PROFILED
    k_check<<<256, 256>>>(z, e);                           // idx 4  (parallelized)
    k_fallback<<<NROWS / BM, 256>>>(z, e);                 // idx 5
    k_gather<<<NROWS / 8, 256>>>(z, out);                  // idx 6
    k_final<<<1, 256>>>(out);                              // idx 7
}

// round 16
// speedup vs baseline: 2.1251x; 1.0744x over previous
#include <cuda_runtime.h>
#include <cuda_bf16.h>
#include <math.h>
#include <stdint.h>

#define NROWS 65536
#define D 256
#define K 1024
#define QSIZE (NROWS*D)
#define CAND_M 6e-4f
#define NCAND 64

// ---------------- scratch ----------------
__device__ __align__(128) float g_eT[K*D];
__device__ __align__(128) float g_en2[K];
__device__ __align__(128) float g_zn2[NROWS];
__device__ int   g_idx[NROWS];
__device__ float g_part[8192];
__device__ int   g_hist[K];
__device__ __align__(128) __nv_bfloat16 g_ebh[K*D];   // bf16(e^T)
__device__ int   g_flag[NROWS];
__device__ int   g_nflag;
__device__ int   g_bad;
__device__ short g_cand[(size_t)NROWS*NCAND];
__device__ int   g_cnt[NROWS];

// ---------------- asm helpers ----------------
__device__ __forceinline__ uint32_t smem_u32(const void* p) {
    uint32_t a;
    asm("{ .reg .u64 t; cvta.to.shared.u64 t, %1; cvt.u32.u64 %0, t; }" : "=r"(a) : "l"(p));
    return a;
}
__device__ __forceinline__ void ldsm4(uint32_t* r, uint32_t addr) {
    asm volatile("ldmatrix.sync.aligned.m8n8.x4.shared.b16 {%0,%1,%2,%3}, [%4];"
        : "=r"(r[0]), "=r"(r[1]), "=r"(r[2]), "=r"(r[3]) : "r"(addr));
}
__device__ __forceinline__ void mma16816(float* c, const uint32_t* a, uint32_t b0, uint32_t b1) {
    asm volatile("mma.sync.aligned.m16n8k16.row.col.f32.bf16.bf16.f32 "
        "{%0,%1,%2,%3}, {%4,%5,%6,%7}, {%8,%9}, {%0,%1,%2,%3};"
        : "+f"(c[0]), "+f"(c[1]), "+f"(c[2]), "+f"(c[3])
        : "r"(a[0]), "r"(a[1]), "r"(a[2]), "r"(a[3]), "r"(b0), "r"(b1));
}
__device__ __forceinline__ void cp16(uint32_t dst, const void* src) {
    asm volatile("cp.async.cg.shared.global [%0], [%1], 16;" :: "r"(dst), "l"(src) : "memory");
}
#define CP_COMMIT() asm volatile("cp.async.commit_group;" ::: "memory")
#define CP_WAIT1()  asm volatile("cp.async.wait_group 1;" ::: "memory")
#define CP_WAIT0()  asm volatile("cp.async.wait_group 0;" ::: "memory")

__device__ __forceinline__ void fma2(unsigned long long& acc,
                                     unsigned long long a, unsigned long long b) {
    asm("fma.rn.f32x2 %0, %1, %2, %0;" : "+l"(acc) : "l"(a), "l"(b));
}
__device__ __forceinline__ unsigned long long pack2(float x) {
    unsigned long long r;
    asm("mov.b64 %0, {%1, %2};" : "=l"(r) : "f"(x), "f"(x));
    return r;
}
__device__ __forceinline__ void unpack2(float& lo, float& hi, unsigned long long v) {
    asm("mov.b64 {%0, %1}, %2;" : "=f"(lo), "=f"(hi) : "l"(v));
}

// ---------------- merged setup: zn2 (2048) + en2/init (4) + prep (256) ----------------
__global__ void k_setup(const float* __restrict__ z, const float* __restrict__ e) {
    int b = blockIdx.x;
    int tid = threadIdx.x;
    if (b < 2048) {
        __shared__ float sz[32][257];
        int row0 = b * 32;
        #pragma unroll
        for (int i = 0; i < 32; i++) {
            int l = i * 256 + tid;
            int r = l >> 8, d = l & 255;
            sz[r][d] = z[(size_t)(row0 + r) * D + d];
        }
        __syncthreads();
        if (tid < 32) {
            float s = 0.f;
            for (int d = 0; d < D; ++d) {
                float v = sz[tid][d];
                s = __fadd_rn(s, __fmul_rn(v, v));
            }
            g_zn2[row0 + tid] = s;
        }
        return;
    }
    if (b < 2052) {
        int t = (b - 2048) * 256 + tid;
        if (t == 0) { g_nflag = 0; g_bad = 0; }
        if (t < K) {
            g_hist[t] = 0;
            float s = 0.f;
            for (int d = 0; d < D; ++d) {
                float v = e[d * K + t];
                s = __fadd_rn(s, __fmul_rn(v, v));
            }
            g_en2[t] = s;
        }
        return;
    }
    __shared__ float t[32][33];
    int bb = b - 2052;
    int kb = (bb & 31) * 32, db = (bb >> 5) * 32;
    int tx = tid & 31, ty = tid >> 5;
    #pragma unroll
    for (int i = 0; i < 32; i += 8)
        t[ty + i][tx] = e[(db + ty + i) * K + kb + tx];
    __syncthreads();
    #pragma unroll
    for (int i = 0; i < 32; i += 8) {
        float v = t[tx][ty + i];
        int off = (kb + ty + i) * D + db + tx;
        g_eT[off] = v;
        g_ebh[off] = __float2bfloat16_rn(v);
    }
}

// ---------------- phaseA: single-product bf16 HMMA + candidate generation ----------------
#define PITCH 528
#define SB_OFF 67584
#define SB_BUF 16896
#define SEN2   101376
#define SDIST  101632
#define SCAND  119040
#define SMEM_TOT 135424

__device__ __forceinline__ void stageB(char* smem, uint32_t sb, int chunk, int buf, int tid) {
    #pragma unroll
    for (int i = 0; i < 4; i++) {
        int lin = i * 256 + tid;
        int r = lin >> 5, s = lin & 31;
        const __nv_bfloat16* src = g_ebh + ((size_t)(chunk * 32 + r) << 8) + (s << 3);
        uint32_t dst = sb + SB_OFF + buf * SB_BUF + r * PITCH + (s << 4);
        cp16(dst, src);
    }
    if (tid < 32)
        *(float*)(smem + SEN2 + buf * 128 + tid * 4) = g_en2[chunk * 32 + tid];
}

__global__ __launch_bounds__(256, 1)
void k_phaseA(const float* __restrict__ z) {
    extern __shared__ char smem[];
    uint32_t sb = smem_u32(smem);
    int tid = threadIdx.x, lane = tid & 31, wid = tid >> 5;
    int warp_m = wid >> 1, warp_n = wid & 1;
    int row0 = blockIdx.x * 128;

    #pragma unroll 4
    for (int i = 0; i < 32; i++) {
        int gi = i * 256 + tid;
        int r = gi >> 6, c4 = (gi & 63) << 2;
        const float4 v = *(const float4*)(z + ((size_t)(row0 + r) << 8) + c4);
        __nv_bfloat16 h0 = __float2bfloat16_rn(v.x), h1 = __float2bfloat16_rn(v.y);
        __nv_bfloat16 h2 = __float2bfloat16_rn(v.z), h3 = __float2bfloat16_rn(v.w);
        uint2 hw;
        hw.x = (uint32_t)__bfloat16_as_ushort(h0) | ((uint32_t)__bfloat16_as_ushort(h1) << 16);
        hw.y = (uint32_t)__bfloat16_as_ushort(h2) | ((uint32_t)__bfloat16_as_ushort(h3) << 16);
        *(uint2*)(smem + r * PITCH + (c4 << 1)) = hw;
    }
    stageB(smem, sb, 0, 0, tid);
    CP_COMMIT();

    uint32_t a_off = sb + (uint32_t)(warp_m * 32 + (lane & 15)) * PITCH + ((lane >> 4) << 4);
    uint32_t b_off = sb + SB_OFF
        + (uint32_t)(warp_n * 16 + (lane & 7) + ((lane >> 4) << 3)) * PITCH
        + (((lane >> 3) & 1) << 4);

    float* sd = (float*)(smem + SDIST);
    short* scand = (short*)(smem + SCAND);
    float rmin = INFINITY;
    int nc = 0, ovf = 0;

    for (int ch = 0; ch < 32; ch++) {
        int buf = ch & 1;
        if (ch + 1 < 32) { stageB(smem, sb, ch + 1, buf ^ 1, tid); CP_COMMIT(); CP_WAIT1(); }
        else CP_WAIT0();
        __syncthreads();

        float acc[2][2][4];
        #pragma unroll
        for (int mt = 0; mt < 2; mt++)
            #pragma unroll
            for (int nt = 0; nt < 2; nt++)
                #pragma unroll
                for (int q = 0; q < 4; q++) acc[mt][nt][q] = 0.f;

        uint32_t bb = b_off + buf * SB_BUF;
        #pragma unroll
        for (int kk = 0; kk < 16; kk++) {
            uint32_t A0[4], A1[4], B[4];
            ldsm4(A0, a_off + kk * 32);
            ldsm4(A1, a_off + kk * 32 + 16 * PITCH);
            ldsm4(B, bb + kk * 32);
            mma16816(acc[0][0], A0, B[0], B[1]);
            mma16816(acc[0][1], A0, B[2], B[3]);
            mma16816(acc[1][0], A1, B[0], B[1]);
            mma16816(acc[1][1], A1, B[2], B[3]);
        }

        const float* en2s = (const float*)(smem + SEN2 + buf * 128);
        #pragma unroll
        for (int mt = 0; mt < 2; mt++) {
            #pragma unroll
            for (int nt = 0; nt < 2; nt++) {
                int cb = warp_n * 16 + nt * 8 + (lane & 3) * 2;
                float e0 = en2s[cb], e1 = en2s[cb + 1];
                #pragma unroll
                for (int half = 0; half < 2; half++) {
                    int r = warp_m * 32 + mt * 16 + half * 8 + (lane >> 2);
                    float2 dp;
                    dp.x = __fsub_rn(e0, 2.0f * acc[mt][nt][half * 2]);
                    dp.y = __fsub_rn(e1, 2.0f * acc[mt][nt][half * 2 + 1]);
                    *(float2*)&sd[r * 34 + cb] = dp;
                }
            }
        }
        __syncthreads();
        if (tid < 128) {
            const float* rowd = &sd[tid * 34];
            float cmin = rowd[0];
            #pragma unroll
            for (int c = 1; c < 32; c++) cmin = fminf(cmin, rowd[c]);
            if (cmin < rmin + CAND_M) {
                float thr = fminf(rmin, cmin) + CAND_M;
                #pragma unroll
                for (int c = 0; c < 32; c++) {
                    if (rowd[c] < thr) {
                        if (nc < NCAND) scand[tid * NCAND + nc] = (short)(ch * 32 + c);
                        else ovf = 1;
                        nc++;
                    }
                }
            }
            rmin = fminf(rmin, cmin);
        }
        __syncthreads();
    }

    if (tid < 128) {
        int row = row0 + tid;
        if (ovf) {
            g_cnt[row] = -1;
            int p = atomicAdd(&g_nflag, 1);
            g_flag[p] = row;
        } else {
            g_cnt[row] = nc;
            for (int c = 0; c < nc; c++)
                g_cand[(size_t)row * NCAND + c] = scand[tid * NCAND + c];
        }
    }
}

// ---------------- k_cand v2: smem-staged exact re-rank ----------------
// per warp: 8 staged e-rows (pitch 260) + z row (260) = 2340 floats; 8 warps = 74880 B
#define CB 8
#define CPITCH 260
#define WARP_FLOATS (CB * CPITCH + CPITCH)
#define KC_SMEM (8 * WARP_FLOATS * 4)

__global__ __launch_bounds__(256, 2)
void k_cand(const float* __restrict__ z) {
    extern __shared__ float cs[];
    int warp = threadIdx.x >> 5, lane = threadIdx.x & 31;
    float* ws = cs + warp * WARP_FLOATS;      // 8 e-rows
    float* zs = ws + CB * CPITCH;             // z row
    int row = blockIdx.x * 8 + warp;
    int cnt = g_cnt[row];
    if (cnt < 0) return;                      // overflow -> rescued

    // stage z row (coalesced)
    const float4* zr4 = (const float4*)(z + ((size_t)row << 8));
    #pragma unroll
    for (int q = lane; q < 64; q += 32)
        ((float4*)zs)[q >> 0] = zr4[q];
    __syncwarp();

    float zn2 = g_zn2[row];
    float bv = INFINITY; int bord = 1 << 20, bc = 0;

    for (int base = 0; base < cnt; base += CB) {
        int nb = min(CB, cnt - base);
        // stage nb candidate e-rows (coalesced float4)
        for (int j = 0; j < nb; j++) {
            int code = (int)g_cand[(size_t)row * NCAND + base + j];
            const float4* er4 = (const float4*)(g_eT + ((size_t)code << 8));
            float4* dst = (float4*)(ws + j * CPITCH);
            #pragma unroll
            for (int q = lane; q < 64; q += 32) dst[q] = er4[q];
        }
        __syncwarp();
        // lanes 0..nb-1 each compute one exact dot from smem (sequential-d fmaf)
        float dist = INFINITY; int code = 0;
        if (lane < nb) {
            code = (int)g_cand[(size_t)row * NCAND + base + lane];
            const float* er = ws + lane * CPITCH;
            float t = 0.f;
            #pragma unroll 8
            for (int d = 0; d < 256; d++)
                t = fmaf(zs[d], er[d], t);
            dist = __fsub_rn(__fadd_rn(zn2, g_en2[code]), 2.0f * t);
        }
        int ord = (lane < nb) ? base + lane : (1 << 20);
        float v = dist; int o = ord, c = code;
        #pragma unroll
        for (int off = 16; off; off >>= 1) {
            float ov = __shfl_xor_sync(0xffffffffu, v, off);
            int oo = __shfl_xor_sync(0xffffffffu, o, off);
            int oc = __shfl_xor_sync(0xffffffffu, c, off);
            if (ov < v || (ov == v && oo < o)) { v = ov; o = oo; c = oc; }
        }
        if (v < bv || (v == bv && o < bord)) { bv = v; bord = o; bc = c; }
        __syncwarp();
    }
    if (lane == 0) g_idx[row] = bc;
}

// ---------------- block-batched exact rescue (overflow rows) ----------------
#define RSP 260
#define RS_SMEM ((32*RSP + 64*RSP + 256 + 256) * 4)

__global__ __launch_bounds__(256, 1)
void k_rescue(const float* __restrict__ z) {
    extern __shared__ float rs[];
    float* sz = rs;
    float* se = rs + 32 * RSP;
    float* mbv = se + 64 * RSP;
    int*   mbi = (int*)(mbv + 256);
    int tid = threadIdx.x;
    int r = tid >> 3, cs2 = tid & 7;
    int n = g_nflag;

    for (int base = blockIdx.x * 32; base < n; base += gridDim.x * 32) {
        int cnt = min(32, n - base);
        for (int i = tid; i < cnt * 64; i += 256) {
            int rr = i >> 6, q = (i & 63) << 2;
            int row = g_flag[base + rr];
            float4 vv = *(const float4*)&z[((size_t)row << 8) + q];
            sz[rr * RSP + q] = vv.x; sz[rr * RSP + q + 1] = vv.y;
            sz[rr * RSP + q + 2] = vv.z; sz[rr * RSP + q + 3] = vv.w;
        }
        float myzn2 = (r < cnt) ? g_zn2[g_flag[base + r]] : 0.f;
        float bv = INFINITY; int bi = 0;
        for (int cc = 0; cc < 16; cc++) {
            __syncthreads();
            for (int i = tid; i < 64 * 64; i += 256) {
                int c = i >> 6, q = (i & 63) << 2;
                float4 vv = *(const float4*)&g_eT[((size_t)(cc * 64 + c) << 8) + q];
                se[c * RSP + q] = vv.x; se[c * RSP + q + 1] = vv.y;
                se[c * RSP + q + 2] = vv.z; se[c * RSP + q + 3] = vv.w;
            }
            __syncthreads();
            if (r < cnt) {
                #pragma unroll
                for (int m = 0; m < 8; m++) {
                    int c = cs2 + 8 * m;
                    float t = 0.f;
                    #pragma unroll 8
                    for (int d = 0; d < 256; d++)
                        t = fmaf(sz[r * RSP + d], se[c * RSP + d], t);
                    int cde = cc * 64 + c;
                    float dist = __fsub_rn(__fadd_rn(myzn2, g_en2[cde]), 2.0f * t);
                    if (dist < bv) { bv = dist; bi = cde; }
                }
            }
        }
        mbv[tid] = bv; mbi[tid] = bi;
        __syncthreads();
        if (tid < cnt) {
            float fb = mbv[tid * 8]; int fi = mbi[tid * 8];
            #pragma unroll
            for (int s2 = 1; s2 < 8; s2++) {
                float vv = mbv[tid * 8 + s2]; int ii = mbi[tid * 8 + s2];
                if (vv < fb || (vv == fb && ii < fi)) { fb = vv; fi = ii; }
            }
            g_idx[g_flag[base + tid]] = fi;
        }
        __syncthreads();
    }
}

// ---------------- parallel exact index checker (256 rows, block per row) ----------------
__global__ void k_check(const float* __restrict__ z, const float* __restrict__ e) {
    __shared__ float srow[256];
    __shared__ float rv[256];
    __shared__ int   ri[256];
    int tid = threadIdx.x;
    int row = blockIdx.x * 256 + 128;
    srow[tid] = z[((size_t)row << 8) + tid];
    __syncthreads();
    float zn2 = g_zn2[row];
    float bv = INFINITY; int bi = 0;
    #pragma unroll
    for (int j = 0; j < 4; j++) {
        int code = j * 256 + tid;
        float t = 0.f;
        #pragma unroll 8
        for (int d = 0; d < 256; d++)
            t = fmaf(srow[d], e[d * K + code], t);
        float dist = __fsub_rn(__fadd_rn(zn2, g_en2[code]), 2.0f * t);
        if (dist < bv) { bv = dist; bi = code; }
    }
    rv[tid] = bv; ri[tid] = bi;
    __syncthreads();
    for (int off = 128; off; off >>= 1) {
        if (tid < off) {
            float ov = rv[tid + off]; int oi = ri[tid + off];
            if (ov < rv[tid] || (ov == rv[tid] && oi < ri[tid])) { rv[tid] = ov; ri[tid] = oi; }
        }
        __syncthreads();
    }
    if (tid == 0 && g_idx[row] != ri[0]) atomicAdd(&g_bad, 1);
}

// ---------------- conditional FFMA2 fp32 fallback (R6, bit-exact) ----------------
#define BM 128
#define BN 128
#define BK 16
#define TM 8
#define TN 8
#define BMP 132

__global__ __launch_bounds__(256, 2)
void k_fallback(const float* __restrict__ z, const float* __restrict__ e) {
    if (g_bad == 0) return;
    __shared__ float s_zT[BK][BMP];
    __shared__ float s_e[BK][BN];
    __shared__ float s_en2[BN];
    __shared__ float m_v[BM][16];
    __shared__ int   m_i[BM][16];

    int tid = threadIdx.x;
    int tx = tid & 15, ty = tid >> 4;
    int row0 = blockIdx.x * BM;

    float bestv[TM]; int besti[TM]; float my_zn2[TM];
    #pragma unroll
    for (int i = 0; i < TM; i++) {
        bestv[i] = INFINITY; besti[i] = 0;
        my_zn2[i] = g_zn2[row0 + ty * TM + i];
    }

    for (int kc = 0; kc < K; kc += BN) {
        __syncthreads();
        if (tid < BN) s_en2[tid] = g_en2[kc + tid];
        unsigned long long acc2[TM][TN / 2];
        #pragma unroll
        for (int i = 0; i < TM; i++)
            #pragma unroll
            for (int j = 0; j < TN / 2; j++) acc2[i][j] = 0ULL;
        for (int dk = 0; dk < D; dk += BK) {
            #pragma unroll
            for (int i = 0; i < 8; i++) {
                int l = i * 256 + tid;
                int r = l >> 4, d = l & 15;
                s_zT[d][r] = z[(size_t)(row0 + r) * D + dk + d];
                int d2 = l >> 7, k2 = l & 127;
                s_e[d2][k2] = e[(dk + d2) * K + kc + k2];
            }
            __syncthreads();
            #pragma unroll
            for (int d = 0; d < BK; d++) {
                float a[TM];
                float4 a0 = *(const float4*)&s_zT[d][ty * TM];
                float4 a1 = *(const float4*)&s_zT[d][ty * TM + 4];
                a[0]=a0.x; a[1]=a0.y; a[2]=a0.z; a[3]=a0.w;
                a[4]=a1.x; a[5]=a1.y; a[6]=a1.z; a[7]=a1.w;
                union { float4 v; unsigned long long u[2]; } bu0, bu1;
                bu0.v = *(const float4*)&s_e[d][tx * TN];
                bu1.v = *(const float4*)&s_e[d][tx * TN + 4];
                unsigned long long b2v[4] = { bu0.u[0], bu0.u[1], bu1.u[0], bu1.u[1] };
                #pragma unroll
                for (int i = 0; i < TM; i++) {
                    unsigned long long a2 = pack2(a[i]);
                    fma2(acc2[i][0], a2, b2v[0]);
                    fma2(acc2[i][1], a2, b2v[1]);
                    fma2(acc2[i][2], a2, b2v[2]);
                    fma2(acc2[i][3], a2, b2v[3]);
                }
            }
            __syncthreads();
        }
        #pragma unroll
        for (int i = 0; i < TM; i++) {
            #pragma unroll
            for (int j2 = 0; j2 < TN / 2; j2++) {
                float t0, t1;
                unpack2(t0, t1, acc2[i][j2]);
                int j = 2 * j2;
                float dist0 = __fsub_rn(__fadd_rn(my_zn2[i], s_en2[tx * TN + j]), 2.0f * t0);
                float dist1 = __fsub_rn(__fadd_rn(my_zn2[i], s_en2[tx * TN + j + 1]), 2.0f * t1);
                int code = kc + tx * TN + j;
                if (dist0 < bestv[i]) { bestv[i] = dist0; besti[i] = code; }
                if (dist1 < bestv[i]) { bestv[i] = dist1; besti[i] = code + 1; }
            }
        }
    }
    __syncthreads();
    #pragma unroll
    for (int i = 0; i < TM; i++) {
        m_v[ty * TM + i][tx] = bestv[i];
        m_i[ty * TM + i][tx] = besti[i];
    }
    __syncthreads();
    if (tid < BM) {
        float bv = m_v[tid][0]; int bi = m_i[tid][0];
        #pragma unroll
        for (int t = 1; t < 16; t++) {
            float v = m_v[tid][t]; int ii = m_i[tid][t];
            if (v < bv || (v == bv && ii < bi)) { bv = v; bi = ii; }
        }
        g_idx[row0 + tid] = bi;
    }
}

// ---------------- gather + losses ----------------
__global__ void k_gather(const float* __restrict__ z, float* __restrict__ out) {
    int warp = threadIdx.x >> 5, lane = threadIdx.x & 31;
    int row = blockIdx.x * 8 + warp;
    int k = g_idx[row];
    if (lane == 0) {
        atomicAdd(&g_hist[k], 1);
        out[QSIZE + row] = (float)k;
    }
    const float* er = &g_eT[k * D];
    const float* zr = z + (size_t)row * D;
    float* qr = out + (size_t)row * D;
    float ss = 0.f;
    #pragma unroll
    for (int d = lane; d < D; d += 32) {
        float q = er[d];
        float zv = zr[d];
        float diff = q - zv;
        ss = fmaf(diff, diff, ss);
        qr[d] = __fadd_rn(zv, __fsub_rn(q, zv));
    }
    #pragma unroll
    for (int off = 16; off; off >>= 1)
        ss += __shfl_xor_sync(0xffffffffu, ss, off);
    __shared__ float wsum[8];
    if (lane == 0) wsum[warp] = ss;
    __syncthreads();
    if (threadIdx.x == 0) {
        float t = 0.f;
        for (int w = 0; w < 8; w++) t += wsum[w];
        g_part[blockIdx.x] = t;
    }
}

__global__ void k_final(float* __restrict__ out) {
    __shared__ double sd2[256];
    __shared__ float sent[256];
    int t = threadIdx.x;
    double s = 0.0;
    for (int i = t; i < 8192; i += 256) s += (double)g_part[i];
    sd2[t] = s;
    float ep = 0.f;
    #pragma unroll
    for (int j = 0; j < 4; j++) {
        int i = t * 4 + j;
        float p = __fmul_rn((float)g_hist[i], 1.0f / 65536.0f);
        ep = __fadd_rn(ep, __fmul_rn(p, logf(__fadd_rn(p, 1e-10f))));
    }
    sent[t] = ep;
    __syncthreads();
    for (int off = 128; off; off >>= 1) {
        if (t < off) {
            sd2[t] += sd2[t + off];
            sent[t] = __fadd_rn(sent[t], sent[t + off]);
        }
        __syncthreads();
    }
    if (t == 0) {
        float vq = (float)(sd2[0] / (double)QSIZE);
        out[QSIZE + NROWS + 0] = vq;
        out[QSIZE + NROWS + 1] = 0.25f * vq;
        out[QSIZE + NROWS + 2] = expf(-sent[0]);
    }
}

extern "C" void kernel_launch(void* const* d_in, const int* in_sizes, int n_in,
                              void* d_out, int out_size) {
    const float* z = (const float*)d_in[0];
    const float* e = (const float*)d_in[1];
    float* out = (float*)d_out;

    cudaFuncSetAttribute(k_phaseA, cudaFuncAttributeMaxDynamicSharedMemorySize, SMEM_TOT);
    cudaFuncSetAttribute(k_rescue, cudaFuncAttributeMaxDynamicSharedMemorySize, RS_SMEM);
    cudaFuncSetAttribute(k_cand, cudaFuncAttributeMaxDynamicSharedMemorySize, KC_SMEM);

    k_setup<<<2308, 256>>>(z, e);                          // idx 0
    k_phaseA<<<NROWS / 128, 256, SMEM_TOT>>>(z);           // idx 1
    k_rescue<<<256, 256, RS_SMEM>>>(z);                    // idx 2
    k_cand<<<NROWS / 8, 256, KC_SMEM>>>(z);                // idx 3  <- PROFILED
    k_check<<<256, 256>>>(z, e);                           // idx 4
    k_fallback<<<NROWS / BM, 256>>>(z, e);                 // idx 5
    k_gather<<<NROWS / 8, 256>>>(z, out);                  // idx 6
    k_final<<<1, 256>>>(out);                              // idx 7
}